// round 11
// baseline (speedup 1.0000x reference)
#include <cuda_runtime.h>
#include <cuda_bf16.h>
#include <cuda_fp16.h>
#include <math.h>

// ---------------- static config ----------------
#define HWP   4096
#define PP    32768
#define DIMC  256
#define CRC   64
#define GCC   32
#define HCC   16
#define N9    9
#define OFFC  18
#define NCLS  80
#define SCALEF 0.25f
#define MULF  5.0f

// ---------------- scratch ----------------
__device__ unsigned g_xn2[PP * DIMC];        // LN'd x, packed bf16 hi|lo<<16
__device__ float  g_qbuf[PP * CRC];
__device__ __half g_kvbuf[16 * HWP * 64];    // interleaved: k ch0-31, v ch32-63
__device__ float  g_tbuf[16 * HWP * GCC];
__device__ float  g_offbuf[16 * HWP * OFFC];
__device__ float  g_attnout[PP * CRC];
__device__ float  g_ybuf[PP * DIMC];

// ---------------- kernel 1: channel-LN + transpose + packed bf16 split --------
__global__ void k_ln(const float* __restrict__ x,
                     const float* __restrict__ gam,
                     const float* __restrict__ bet)
{
    __shared__ float s[DIMC][33];
    __shared__ float red[2][8][32];
    __shared__ float smean[32], srstd[32];

    int p0 = blockIdx.x * 32;
    int b  = p0 >> 12;
    int hw0 = p0 & 4095;
    int tid = threadIdx.x;
    int tx = tid & 31, ty = tid >> 5;

    const float* xb = x + (size_t)b * DIMC * HWP + hw0;
    for (int c = ty; c < DIMC; c += 8)
        s[c][tx] = xb[c * HWP + tx];
    __syncthreads();

    float sum = 0.f, sq = 0.f;
    for (int c = ty; c < DIMC; c += 8) {
        float v = s[c][tx];
        sum += v; sq += v * v;
    }
    red[0][ty][tx] = sum; red[1][ty][tx] = sq;
    __syncthreads();
    if (ty == 0) {
        float s1 = 0.f, s2 = 0.f;
        #pragma unroll
        for (int j = 0; j < 8; j++) { s1 += red[0][j][tx]; s2 += red[1][j][tx]; }
        float m = s1 * (1.f / 256.f);
        float v = s2 * (1.f / 256.f) - m * m;
        smean[tx] = m;
        srstd[tx] = rsqrtf(v + 1e-5f);
    }
    __syncthreads();

    float gg = gam[tid], bb = bet[tid];
    for (int pl = 0; pl < 32; pl++) {
        float v = (s[tid][pl] - smean[pl]) * srstd[pl] * gg + bb;
        __nv_bfloat16 h = __float2bfloat16(v);
        __nv_bfloat16 l = __float2bfloat16(v - __bfloat162float(h));
        unsigned hb_ = *(unsigned short*)&h;
        unsigned lb_ = *(unsigned short*)&l;
        g_xn2[(size_t)(p0 + pl) * DIMC + tid] = hb_ | (lb_ << 16);
    }
}

// ---------------- helpers ----------------
__device__ __forceinline__ void cvt_pair(float x0, float x1,
                                         unsigned& hi, unsigned& lo)
{
    __nv_bfloat16 h0 = __float2bfloat16(x0);
    __nv_bfloat16 h1 = __float2bfloat16(x1);
    float r0 = x0 - __bfloat162float(h0);
    float r1 = x1 - __bfloat162float(h1);
    __nv_bfloat16 l0 = __float2bfloat16(r0);
    __nv_bfloat16 l1 = __float2bfloat16(r1);
    unsigned short u0 = *(unsigned short*)&h0, u1 = *(unsigned short*)&h1;
    unsigned short v0 = *(unsigned short*)&l0, v1 = *(unsigned short*)&l1;
    hi = (unsigned)u0 | ((unsigned)u1 << 16);
    lo = (unsigned)v0 | ((unsigned)v1 << 16);
}

__device__ __forceinline__ void mma_bf16_v(float* c,
                                           unsigned a0, unsigned a1, unsigned a2, unsigned a3,
                                           unsigned b0, unsigned b1)
{
    asm volatile(
        "mma.sync.aligned.m16n8k16.row.col.f32.bf16.bf16.f32 "
        "{%0,%1,%2,%3}, {%4,%5,%6,%7}, {%8,%9}, {%0,%1,%2,%3};\n"
        : "+f"(c[0]), "+f"(c[1]), "+f"(c[2]), "+f"(c[3])
        : "r"(a0), "r"(a1), "r"(a2), "r"(a3), "r"(b0), "r"(b1));
}
#define MMA_BF16 mma_bf16_v

// ---------------- GEMM 0: qkv from packed A ------------------------------
__global__ void __launch_bounds__(256) k_gemm0(const float* __restrict__ Bw)
{
    constexpr int K = 256, Ntot = 192;

    __shared__ unsigned Ah[128][20], Al[128][20];
    __shared__ unsigned Bh[64][20],  Bl[64][20];

    int tid = threadIdx.x;
    int lane = tid & 31;
    int warpId = tid >> 5;
    int warpM = warpId & 3;
    int warpN = warpId >> 2;
    int row0 = blockIdx.y * 128, col0 = blockIdx.x * 64;

    float acc[2][4][4];
    #pragma unroll
    for (int mt = 0; mt < 2; mt++)
        #pragma unroll
        for (int nt = 0; nt < 4; nt++)
            #pragma unroll
            for (int e = 0; e < 4; e++) acc[mt][nt][e] = 0.f;

    uint4 pk[4];
    float4 pb[2];

    // A chunk: 128 rows x 32 packed uints = 1024 uint4, 4 per thread
    #pragma unroll
    for (int i = 0; i < 4; i++) {
        int id = tid + i * 256;
        int row = id >> 3, fq = id & 7;
        pk[i] = *(const uint4*)(g_xn2 + (size_t)(row0 + row) * K + fq * 4);
    }
    #pragma unroll
    for (int i = 0; i < 2; i++) {
        int id = tid + i * 256;
        int brow = id >> 3, bf = id & 7;
        pb[i] = make_float4(0.f, 0.f, 0.f, 0.f);
        if (col0 + brow < Ntot)
            pb[i] = *(const float4*)(Bw + (size_t)(col0 + brow) * K + bf * 4);
    }

    for (int k0 = 0; k0 < K; k0 += 32) {
        #pragma unroll
        for (int i = 0; i < 4; i++) {
            int id = tid + i * 256;
            int row = id >> 3, fq = id & 7;
            uint4 U = pk[i];
            Ah[row][fq * 2]     = __byte_perm(U.x, U.y, 0x5410);
            Ah[row][fq * 2 + 1] = __byte_perm(U.z, U.w, 0x5410);
            Al[row][fq * 2]     = __byte_perm(U.x, U.y, 0x7632);
            Al[row][fq * 2 + 1] = __byte_perm(U.z, U.w, 0x7632);
        }
        #pragma unroll
        for (int i = 0; i < 2; i++) {
            int id = tid + i * 256;
            int brow = id >> 3, bf = id & 7;
            unsigned h0, l0, h1, l1;
            float4 v = pb[i];
            cvt_pair(v.x, v.y, h0, l0);
            cvt_pair(v.z, v.w, h1, l1);
            Bh[brow][bf * 2] = h0; Bh[brow][bf * 2 + 1] = h1;
            Bl[brow][bf * 2] = l0; Bl[brow][bf * 2 + 1] = l1;
        }
        __syncthreads();

        if (k0 + 32 < K) {
            #pragma unroll
            for (int i = 0; i < 4; i++) {
                int id = tid + i * 256;
                int row = id >> 3, fq = id & 7;
                pk[i] = *(const uint4*)(g_xn2 + (size_t)(row0 + row) * K + (k0 + 32) + fq * 4);
            }
            #pragma unroll
            for (int i = 0; i < 2; i++) {
                int id = tid + i * 256;
                int brow = id >> 3, bf = id & 7;
                pb[i] = make_float4(0.f, 0.f, 0.f, 0.f);
                if (col0 + brow < Ntot)
                    pb[i] = *(const float4*)(Bw + (size_t)(col0 + brow) * K + (k0 + 32) + bf * 4);
            }
        }

        #pragma unroll
        for (int kk = 0; kk < 2; kk++) {
            int kb = kk * 8 + (lane & 3);
            unsigned ah[2][4], al[2][4];
            #pragma unroll
            for (int mt = 0; mt < 2; mt++) {
                int ar = warpM * 32 + mt * 16 + (lane >> 2);
                ah[mt][0] = Ah[ar][kb];     ah[mt][1] = Ah[ar + 8][kb];
                ah[mt][2] = Ah[ar][kb + 4]; ah[mt][3] = Ah[ar + 8][kb + 4];
                al[mt][0] = Al[ar][kb];     al[mt][1] = Al[ar + 8][kb];
                al[mt][2] = Al[ar][kb + 4]; al[mt][3] = Al[ar + 8][kb + 4];
            }
            #pragma unroll
            for (int nt = 0; nt < 4; nt++) {
                int br = warpN * 32 + nt * 8 + (lane >> 2);
                unsigned bh0 = Bh[br][kb], bh1 = Bh[br][kb + 4];
                unsigned bl0 = Bl[br][kb], bl1 = Bl[br][kb + 4];
                #pragma unroll
                for (int mt = 0; mt < 2; mt++) {
                    MMA_BF16(acc[mt][nt], ah[mt][0], ah[mt][1], ah[mt][2], ah[mt][3], bh0, bh1);
                    MMA_BF16(acc[mt][nt], ah[mt][0], ah[mt][1], ah[mt][2], ah[mt][3], bl0, bl1);
                    MMA_BF16(acc[mt][nt], al[mt][0], al[mt][1], al[mt][2], al[mt][3], bh0, bh1);
                }
            }
        }
        __syncthreads();
    }

    #pragma unroll
    for (int mt = 0; mt < 2; mt++) {
        #pragma unroll
        for (int nt = 0; nt < 4; nt++) {
            #pragma unroll
            for (int e = 0; e < 4; e++) {
                int p = row0 + warpM * 32 + mt * 16 + (lane >> 2) + ((e >= 2) ? 8 : 0);
                int o = col0 + warpN * 32 + nt * 8 + 2 * (lane & 3) + (e & 1);
                float v = acc[mt][nt][e];
                int bidx = p >> 12, hw = p & 4095;
                if (o < 64) {
                    g_qbuf[p * 64 + o] = v;
                } else if (o < 128) {
                    int c = o - 64;
                    g_kvbuf[((size_t)(bidx * 2 + (c >> 5)) * HWP + hw) * 64 + (c & 31)] =
                        __float2half(v);
                } else {
                    int c = o - 128;
                    g_kvbuf[((size_t)(bidx * 2 + (c >> 5)) * HWP + hw) * 64 + 32 + (c & 31)] =
                        __float2half(v);
                }
            }
        }
    }
}

// ---------------- GEMM modes 1/2 (fp32 A, cvt staging + prefetch) --------------
template<int MODE>
__global__ void __launch_bounds__(256) k_gemm(const float* __restrict__ Bw,
                                              const float* __restrict__ bias,
                                              const float* __restrict__ resid,
                                              float* __restrict__ outp)
{
    constexpr int K    = (MODE == 1) ? 64 : 256;
    constexpr int Ntot = (MODE == 1) ? 256 : 80;
    const float* A = (MODE == 1) ? g_attnout : g_ybuf;

    __shared__ unsigned Ah[128][20], Al[128][20];
    __shared__ unsigned Bh[64][20],  Bl[64][20];

    int tid = threadIdx.x;
    int lane = tid & 31;
    int warpId = tid >> 5;
    int warpM = warpId & 3;
    int warpN = warpId >> 2;
    int row0 = blockIdx.y * 128, col0 = blockIdx.x * 64;

    float acc[2][4][4];
    #pragma unroll
    for (int mt = 0; mt < 2; mt++)
        #pragma unroll
        for (int nt = 0; nt < 4; nt++)
            #pragma unroll
            for (int e = 0; e < 4; e++) acc[mt][nt][e] = 0.f;

    float4 pa[4], pb[2];
    #pragma unroll
    for (int i = 0; i < 4; i++) {
        int id = tid + i * 256;
        int row = id >> 3, f = id & 7;
        pa[i] = *(const float4*)(A + (size_t)(row0 + row) * K + f * 4);
    }
    #pragma unroll
    for (int i = 0; i < 2; i++) {
        int id = tid + i * 256;
        int row = id >> 3, f = id & 7;
        pb[i] = make_float4(0.f, 0.f, 0.f, 0.f);
        if (col0 + row < Ntot)
            pb[i] = *(const float4*)(Bw + (size_t)(col0 + row) * K + f * 4);
    }

    for (int k0 = 0; k0 < K; k0 += 32) {
        #pragma unroll
        for (int i = 0; i < 4; i++) {
            int id = tid + i * 256;
            int row = id >> 3, f = id & 7;
            unsigned h0, l0, h1, l1;
            cvt_pair(pa[i].x, pa[i].y, h0, l0);
            cvt_pair(pa[i].z, pa[i].w, h1, l1);
            Ah[row][f * 2] = h0; Ah[row][f * 2 + 1] = h1;
            Al[row][f * 2] = l0; Al[row][f * 2 + 1] = l1;
        }
        #pragma unroll
        for (int i = 0; i < 2; i++) {
            int id = tid + i * 256;
            int row = id >> 3, f = id & 7;
            unsigned h0, l0, h1, l1;
            cvt_pair(pb[i].x, pb[i].y, h0, l0);
            cvt_pair(pb[i].z, pb[i].w, h1, l1);
            Bh[row][f * 2] = h0; Bh[row][f * 2 + 1] = h1;
            Bl[row][f * 2] = l0; Bl[row][f * 2 + 1] = l1;
        }
        __syncthreads();

        if (k0 + 32 < K) {
            #pragma unroll
            for (int i = 0; i < 4; i++) {
                int id = tid + i * 256;
                int row = id >> 3, f = id & 7;
                pa[i] = *(const float4*)(A + (size_t)(row0 + row) * K + (k0 + 32) + f * 4);
            }
            #pragma unroll
            for (int i = 0; i < 2; i++) {
                int id = tid + i * 256;
                int row = id >> 3, f = id & 7;
                pb[i] = make_float4(0.f, 0.f, 0.f, 0.f);
                if (col0 + row < Ntot)
                    pb[i] = *(const float4*)(Bw + (size_t)(col0 + row) * K + (k0 + 32) + f * 4);
            }
        }

        #pragma unroll
        for (int kk = 0; kk < 2; kk++) {
            int kb = kk * 8 + (lane & 3);
            unsigned ah[2][4], al[2][4];
            #pragma unroll
            for (int mt = 0; mt < 2; mt++) {
                int ar = warpM * 32 + mt * 16 + (lane >> 2);
                ah[mt][0] = Ah[ar][kb];     ah[mt][1] = Ah[ar + 8][kb];
                ah[mt][2] = Ah[ar][kb + 4]; ah[mt][3] = Ah[ar + 8][kb + 4];
                al[mt][0] = Al[ar][kb];     al[mt][1] = Al[ar + 8][kb];
                al[mt][2] = Al[ar][kb + 4]; al[mt][3] = Al[ar + 8][kb + 4];
            }
            #pragma unroll
            for (int nt = 0; nt < 4; nt++) {
                int br = warpN * 32 + nt * 8 + (lane >> 2);
                unsigned bh0 = Bh[br][kb], bh1 = Bh[br][kb + 4];
                unsigned bl0 = Bl[br][kb], bl1 = Bl[br][kb + 4];
                #pragma unroll
                for (int mt = 0; mt < 2; mt++) {
                    MMA_BF16(acc[mt][nt], ah[mt][0], ah[mt][1], ah[mt][2], ah[mt][3], bh0, bh1);
                    MMA_BF16(acc[mt][nt], ah[mt][0], ah[mt][1], ah[mt][2], ah[mt][3], bl0, bl1);
                    MMA_BF16(acc[mt][nt], al[mt][0], al[mt][1], al[mt][2], al[mt][3], bh0, bh1);
                }
            }
        }
        __syncthreads();
    }

    #pragma unroll
    for (int mt = 0; mt < 2; mt++) {
        #pragma unroll
        for (int nt = 0; nt < 4; nt++) {
            #pragma unroll
            for (int e = 0; e < 4; e++) {
                int p = row0 + warpM * 32 + mt * 16 + (lane >> 2) + ((e >= 2) ? 8 : 0);
                int o = col0 + warpN * 32 + nt * 8 + 2 * (lane & 3) + (e & 1);
                float v = acc[mt][nt][e];
                int bidx = p >> 12, hw = p & 4095;
                if (MODE == 1) {
                    g_ybuf[(size_t)p * DIMC + o] =
                        v + bias[o] + resid[(size_t)bidx * DIMC * HWP + o * HWP + hw];
                } else {
                    if (o < Ntot)
                        outp[(size_t)bidx * NCLS * HWP + o * HWP + hw] = v + bias[o];
                }
            }
        }
    }
}

// ---------------- kernel 3: smem-tiled depthwise 3x3 + LN(32) + GELU ----------
__global__ void __launch_bounds__(256, 2) k_dw(const float* __restrict__ wdw,
                                               const float* __restrict__ g2,
                                               const float* __restrict__ b2)
{
    extern __shared__ float4 st4[];
    __shared__ float sw[GCC * 9];
    __shared__ float sg[GCC], sb[GCC];

    int bg = blockIdx.x >> 4;
    int h0 = (blockIdx.x & 15) * 4;
    int b = bg >> 1, g = bg & 1;
    int tid = threadIdx.x;

    for (int i = tid; i < GCC * 9; i += 256) sw[i] = wdw[i];
    if (tid < GCC) { sg[tid] = g2[tid]; sb[tid] = b2[tid]; }
    for (int i = tid; i < 3168; i += 256) st4[i] = make_float4(0.f, 0.f, 0.f, 0.f);
    __syncthreads();

    for (int i = tid; i < 3072; i += 256) {
        int c4 = i & 7, col = (i >> 3) & 63, r = i >> 9;
        int gr = h0 - 1 + r;
        if ((unsigned)gr < 64u)
            st4[(c4 * 6 + r) * 66 + col + 1] =
                *(const float4*)(g_qbuf + ((size_t)(b * HWP + gr * 64 + col)) * CRC + g * GCC + c4 * 4);
    }
    __syncthreads();

    int col = tid & 63;
    int row = tid >> 6;
    int h = h0 + row;

    float acc[GCC];
    #pragma unroll
    for (int c = 0; c < GCC; c++) acc[c] = 0.f;

    #pragma unroll
    for (int ky = 0; ky < 3; ky++) {
        #pragma unroll
        for (int kx = 0; kx < 3; kx++) {
            int kidx = ky * 3 + kx;
            #pragma unroll
            for (int c4 = 0; c4 < 8; c4++) {
                float4 v = st4[(c4 * 6 + row + ky) * 66 + col + kx];
                acc[c4 * 4 + 0] += v.x * sw[(c4 * 4 + 0) * 9 + kidx];
                acc[c4 * 4 + 1] += v.y * sw[(c4 * 4 + 1) * 9 + kidx];
                acc[c4 * 4 + 2] += v.z * sw[(c4 * 4 + 2) * 9 + kidx];
                acc[c4 * 4 + 3] += v.w * sw[(c4 * 4 + 3) * 9 + kidx];
            }
        }
    }

    float m = 0.f;
    #pragma unroll
    for (int c = 0; c < GCC; c++) m += acc[c];
    m *= (1.f / GCC);
    float v = 0.f;
    #pragma unroll
    for (int c = 0; c < GCC; c++) { float d = acc[c] - m; v += d * d; }
    float rs = rsqrtf(v * (1.f / GCC) + 1e-5f);

    float* dst = g_tbuf + ((size_t)bg * HWP + h * 64 + col) * GCC;
    #pragma unroll
    for (int c = 0; c < GCC; c++) {
        float t = (acc[c] - m) * rs * sg[c] + sb[c];
        dst[c] = 0.5f * t * (1.f + erff(t * 0.70710678118654752f));
    }
}

// ---------------- kernel 4: smem-tiled 3x3 conv (32->18), 2 rows/block --------
__global__ void __launch_bounds__(256) k_off(const float* __restrict__ woff,
                                             const float* __restrict__ boff,
                                             const float* __restrict__ offset)
{
    extern __shared__ float4 dyn4[];
    float4* st4 = dyn4;
    float*  sw  = (float*)(dyn4 + 2112);
    float4* sw4 = (float4*)sw;

    int bg = blockIdx.x >> 5;
    int h0 = (blockIdx.x & 31) * 2;
    int tid = threadIdx.x;

    for (int i = tid; i < OFFC * GCC * 9; i += 256) {
        int o = i / (GCC * 9); int rem = i - o * (GCC * 9);
        int c = rem / 9; int kidx = rem - c * 9;
        sw[(kidx * OFFC + o) * GCC + c] = woff[i];
    }
    for (int i = tid; i < 2112; i += 256) st4[i] = make_float4(0.f, 0.f, 0.f, 0.f);
    __syncthreads();

    for (int i = tid; i < 2048; i += 256) {
        int c4 = i & 7, col = (i >> 3) & 63, r = i >> 9;
        int gr = h0 - 1 + r;
        if ((unsigned)gr < 64u)
            st4[(c4 * 4 + r) * 66 + col + 1] =
                *(const float4*)(g_tbuf + ((size_t)(bg * HWP + gr * 64 + col)) * GCC + c4 * 4);
    }
    __syncthreads();

    int col = tid & 63;
    int og  = (tid >> 6) & 1;
    int row = tid >> 7;
    int h = h0 + row;
    int b = bg >> 1;

    float acc[9];
    #pragma unroll
    for (int o = 0; o < 9; o++) acc[o] = boff[og * 9 + o];

    #pragma unroll
    for (int c4 = 0; c4 < 8; c4++) {
        #pragma unroll
        for (int ky = 0; ky < 3; ky++) {
            const float4* trow = &st4[(c4 * 4 + row + ky) * 66];
            float4 t[3];
            t[0] = trow[col]; t[1] = trow[col + 1]; t[2] = trow[col + 2];
            #pragma unroll
            for (int kx = 0; kx < 3; kx++) {
                int kidx = ky * 3 + kx;
                #pragma unroll
                for (int o = 0; o < 9; o++) {
                    float4 w = sw4[(kidx * OFFC + og * 9 + o) * 8 + c4];
                    acc[o] += t[kx].x * w.x + t[kx].y * w.y +
                              t[kx].z * w.z + t[kx].w * w.w;
                }
            }
        }
    }

    int hw = h * 64 + col;
    const float* ofs = offset + (size_t)b * OFFC * HWP + hw;
    float* dst = g_offbuf + ((size_t)bg * HWP + hw) * OFFC + og * 9;
    #pragma unroll
    for (int o = 0; o < 9; o++)
        dst[o] = tanhf(acc[o]) * MULF + ofs[(og * 9 + o) * HWP];
}

// ---------------- kernel 5: deformable gather + attention (interleaved kv) ----
// Line layout: g_kvbuf[bg][hw][64]: k ch0-31, v ch32-63 (one 128B L1 line).
__device__ __forceinline__ void samp16kv(const __half* __restrict__ bufh,
                                         int y, int x, float w, float s[16])
{
    if ((unsigned)x < 64u && (unsigned)y < 64u) {
        const uint4* q = (const uint4*)(bufh + (size_t)(y * 64 + x) * 64);
        uint4 u0 = q[0], u1 = q[1];
        const __half2* h0 = (const __half2*)&u0;
        const __half2* h1 = (const __half2*)&u1;
        #pragma unroll
        for (int i = 0; i < 4; i++) {
            float2 f = __half22float2(h0[i]);
            s[2 * i]     += w * f.x;
            s[2 * i + 1] += w * f.y;
        }
        #pragma unroll
        for (int i = 0; i < 4; i++) {
            float2 f = __half22float2(h1[i]);
            s[8 + 2 * i]     += w * f.x;
            s[8 + 2 * i + 1] += w * f.y;
        }
    }
}

__global__ void k_attn(const float* __restrict__ rpb)
{
    int idx = blockIdx.x * blockDim.x + threadIdx.x;
    int nh = idx & 3;
    int p  = idx >> 2;
    int b = p >> 12, hw = p & 4095;
    int g = nh >> 1, hb = (nh & 1) * 16;
    int bg = b * 2 + g;

    float q[16];
    const float* qp = g_qbuf + (size_t)p * CRC + nh * HCC;
    #pragma unroll
    for (int i = 0; i < 16; i++) q[i] = qp[i] * SCALEF;

    const float* off = g_offbuf + (size_t)(bg * HWP + hw) * OFFC;
    const __half* kb = g_kvbuf + (size_t)bg * HWP * 64 + hb;
    const __half* vb = kb + 32;
    const float* rp = rpb + nh * (N9 * HCC);

    int ix[N9], iy[N9];
    float fx[N9], fy[N9], logit[N9];

    #pragma unroll
    for (int n = 0; n < N9; n++) {
        float row = off[2 * n], col = off[2 * n + 1];
        float xf = floorf(col), yf = floorf(row);
        ix[n] = (int)xf; iy[n] = (int)yf;
        fx[n] = col - xf; fy[n] = row - yf;

        float w00 = (1.f - fx[n]) * (1.f - fy[n]);
        float w10 = fx[n] * (1.f - fy[n]);
        float w01 = (1.f - fx[n]) * fy[n];
        float w11 = fx[n] * fy[n];

        float s[16];
        #pragma unroll
        for (int i = 0; i < 16; i++) s[i] = 0.f;
        samp16kv(kb, iy[n],     ix[n],     w00, s);
        samp16kv(kb, iy[n],     ix[n] + 1, w10, s);
        samp16kv(kb, iy[n] + 1, ix[n],     w01, s);
        samp16kv(kb, iy[n] + 1, ix[n] + 1, w11, s);

        float l = 0.f;
        const float* rpn = rp + n * HCC;
        #pragma unroll
        for (int i = 0; i < 16; i++) l += q[i] * (s[i] + rpn[i]);
        logit[n] = l;
    }

    float mx = logit[0];
    #pragma unroll
    for (int n = 1; n < N9; n++) mx = fmaxf(mx, logit[n]);
    float sum = 0.f;
    #pragma unroll
    for (int n = 0; n < N9; n++) { logit[n] = expf(logit[n] - mx); sum += logit[n]; }
    float inv = 1.f / sum;

    float o16[16];
    #pragma unroll
    for (int i = 0; i < 16; i++) o16[i] = 0.f;

    #pragma unroll
    for (int n = 0; n < N9; n++) {
        float wn = logit[n] * inv;
        float w00 = (1.f - fx[n]) * (1.f - fy[n]) * wn;
        float w10 = fx[n] * (1.f - fy[n]) * wn;
        float w01 = (1.f - fx[n]) * fy[n] * wn;
        float w11 = fx[n] * fy[n] * wn;
        samp16kv(vb, iy[n],     ix[n],     w00, o16);
        samp16kv(vb, iy[n],     ix[n] + 1, w10, o16);
        samp16kv(vb, iy[n] + 1, ix[n],     w01, o16);
        samp16kv(vb, iy[n] + 1, ix[n] + 1, w11, o16);
    }

    float* dst = g_attnout + (size_t)p * CRC + nh * HCC;
    #pragma unroll
    for (int i = 0; i < 16; i++) dst[i] = o16[i];
}

// ---------------- launch ----------------
extern "C" void kernel_launch(void* const* d_in, const int* in_sizes, int n_in,
                              void* d_out, int out_size)
{
    const float* x      = (const float*)d_in[0];
    const float* offset = (const float*)d_in[1];
    const float* ln1_g  = (const float*)d_in[2];
    const float* ln1_b  = (const float*)d_in[3];
    const float* w_qkv  = (const float*)d_in[4];
    const float* w_dw   = (const float*)d_in[5];
    const float* ln2_g  = (const float*)d_in[6];
    const float* ln2_b  = (const float*)d_in[7];
    const float* w_off  = (const float*)d_in[8];
    const float* b_off  = (const float*)d_in[9];
    const float* rpb    = (const float*)d_in[10];
    const float* w_proj = (const float*)d_in[11];
    const float* b_proj = (const float*)d_in[12];
    const float* w_cls  = (const float*)d_in[13];
    const float* b_cls  = (const float*)d_in[14];
    float* out = (float*)d_out;

    const int dwSmem  = 3168 * 16;
    const int offSmem = 2112 * 16 + 5184 * 4;
    static int configured = 0;
    if (!configured) {
        cudaFuncSetAttribute(k_dw,  cudaFuncAttributeMaxDynamicSharedMemorySize, dwSmem);
        cudaFuncSetAttribute(k_off, cudaFuncAttributeMaxDynamicSharedMemorySize, offSmem);
        configured = 1;
    }

    k_ln<<<PP / 32, 256>>>(x, ln1_g, ln1_b);
    k_gemm0<<<dim3(3, PP / 128), 256>>>(w_qkv);
    k_dw<<<16 * 16, 256, dwSmem>>>(w_dw, ln2_g, ln2_b);
    k_off<<<16 * 32, 256, offSmem>>>(w_off, b_off, offset);
    k_attn<<<(PP * 4) / 128, 128>>>(rpb);
    k_gemm<1><<<dim3(4, PP / 128), 256>>>(w_proj, b_proj, x, nullptr);
    k_gemm<2><<<dim3(2, PP / 128), 256>>>(w_cls, b_cls, nullptr, out);
}

// round 12
// speedup vs baseline: 1.0540x; 1.0540x over previous
#include <cuda_runtime.h>
#include <cuda_bf16.h>
#include <cuda_fp16.h>
#include <math.h>

// ---------------- static config ----------------
#define HWP   4096
#define PP    32768
#define DIMC  256
#define CRC   64
#define GCC   32
#define HCC   16
#define N9    9
#define OFFC  18
#define NCLS  80
#define SCALEF 0.25f
#define MULF  5.0f

// ---------------- scratch ----------------
__device__ float  g_xn[PP * DIMC];
__device__ float  g_qbuf[PP * CRC];
__device__ __half g_kbufh[16 * HWP * GCC];
__device__ __half g_vbufh[16 * HWP * GCC];
__device__ float  g_tbuf[16 * HWP * GCC];
__device__ float  g_offbuf[16 * HWP * OFFC];
__device__ float  g_attnout[PP * CRC];
__device__ float  g_ybuf[PP * DIMC];

// ---------------- kernel 1: channel-LN + NCHW -> [P,C] transpose ----------------
__global__ void k_ln(const float* __restrict__ x,
                     const float* __restrict__ gam,
                     const float* __restrict__ bet)
{
    __shared__ float s[DIMC][33];
    __shared__ float red[2][8][32];
    __shared__ float smean[32], srstd[32];

    int p0 = blockIdx.x * 32;
    int b  = p0 >> 12;
    int hw0 = p0 & 4095;
    int tid = threadIdx.x;
    int tx = tid & 31, ty = tid >> 5;

    const float* xb = x + (size_t)b * DIMC * HWP + hw0;
    for (int c = ty; c < DIMC; c += 8)
        s[c][tx] = xb[c * HWP + tx];
    __syncthreads();

    float sum = 0.f, sq = 0.f;
    for (int c = ty; c < DIMC; c += 8) {
        float v = s[c][tx];
        sum += v; sq += v * v;
    }
    red[0][ty][tx] = sum; red[1][ty][tx] = sq;
    __syncthreads();
    if (ty == 0) {
        float s1 = 0.f, s2 = 0.f;
        #pragma unroll
        for (int j = 0; j < 8; j++) { s1 += red[0][j][tx]; s2 += red[1][j][tx]; }
        float m = s1 * (1.f / 256.f);
        float v = s2 * (1.f / 256.f) - m * m;
        smean[tx] = m;
        srstd[tx] = rsqrtf(v + 1e-5f);
    }
    __syncthreads();

    float gg = gam[tid], bb = bet[tid];
    for (int pl = 0; pl < 32; pl++) {
        g_xn[(size_t)(p0 + pl) * DIMC + tid] =
            (s[tid][pl] - smean[pl]) * srstd[pl] * gg + bb;
    }
}

// ---------------- helpers: bf16 split + mma ----------------
__device__ __forceinline__ void cvt_pair(float x0, float x1,
                                         unsigned& hi, unsigned& lo)
{
    __nv_bfloat16 h0 = __float2bfloat16(x0);
    __nv_bfloat16 h1 = __float2bfloat16(x1);
    float r0 = x0 - __bfloat162float(h0);
    float r1 = x1 - __bfloat162float(h1);
    __nv_bfloat16 l0 = __float2bfloat16(r0);
    __nv_bfloat16 l1 = __float2bfloat16(r1);
    unsigned short u0 = *(unsigned short*)&h0, u1 = *(unsigned short*)&h1;
    unsigned short v0 = *(unsigned short*)&l0, v1 = *(unsigned short*)&l1;
    hi = (unsigned)u0 | ((unsigned)u1 << 16);
    lo = (unsigned)v0 | ((unsigned)v1 << 16);
}

__device__ __forceinline__ void mma_bf16(float* c,
                                         unsigned a0, unsigned a1, unsigned a2, unsigned a3,
                                         unsigned b0, unsigned b1)
{
    asm volatile(
        "mma.sync.aligned.m16n8k16.row.col.f32.bf16.bf16.f32 "
        "{%0,%1,%2,%3}, {%4,%5,%6,%7}, {%8,%9}, {%0,%1,%2,%3};\n"
        : "+f"(c[0]), "+f"(c[1]), "+f"(c[2]), "+f"(c[3])
        : "r"(a0), "r"(a1), "r"(a2), "r"(a3), "r"(b0), "r"(b1));
}

// ---------------- tensor-core GEMM (bf16 split, 3xMMA) with reg prefetch -------
template<int MODE>
__global__ void __launch_bounds__(256) k_gemm(const float* __restrict__ Bw,
                                              const float* __restrict__ bias,
                                              const float* __restrict__ resid,
                                              float* __restrict__ outp)
{
    constexpr int K    = (MODE == 1) ? 64 : 256;
    constexpr int Ntot = (MODE == 0) ? 192 : (MODE == 1) ? 256 : 80;
    const float* A = (MODE == 0) ? g_xn : (MODE == 1) ? g_attnout : g_ybuf;

    __shared__ unsigned Ah[128][20], Al[128][20];
    __shared__ unsigned Bh[64][20],  Bl[64][20];

    int tid = threadIdx.x;
    int lane = tid & 31;
    int warpId = tid >> 5;
    int warpM = warpId & 3;
    int warpN = warpId >> 2;
    int row0 = blockIdx.y * 128, col0 = blockIdx.x * 64;

    float acc[2][4][4];
    #pragma unroll
    for (int mt = 0; mt < 2; mt++)
        #pragma unroll
        for (int nt = 0; nt < 4; nt++)
            #pragma unroll
            for (int e = 0; e < 4; e++) acc[mt][nt][e] = 0.f;

    float4 pa[4], pb[2];
    #pragma unroll
    for (int i = 0; i < 4; i++) {
        int id = tid + i * 256;
        int row = id >> 3, f = id & 7;
        pa[i] = *(const float4*)(A + (size_t)(row0 + row) * K + 0 + f * 4);
    }
    #pragma unroll
    for (int i = 0; i < 2; i++) {
        int id = tid + i * 256;
        int row = id >> 3, f = id & 7;
        pb[i] = make_float4(0.f, 0.f, 0.f, 0.f);
        if (col0 + row < Ntot)
            pb[i] = *(const float4*)(Bw + (size_t)(col0 + row) * K + 0 + f * 4);
    }

    for (int k0 = 0; k0 < K; k0 += 32) {
        #pragma unroll
        for (int i = 0; i < 4; i++) {
            int id = tid + i * 256;
            int row = id >> 3, f = id & 7;
            unsigned h0, l0, h1, l1;
            cvt_pair(pa[i].x, pa[i].y, h0, l0);
            cvt_pair(pa[i].z, pa[i].w, h1, l1);
            Ah[row][f * 2] = h0; Ah[row][f * 2 + 1] = h1;
            Al[row][f * 2] = l0; Al[row][f * 2 + 1] = l1;
        }
        #pragma unroll
        for (int i = 0; i < 2; i++) {
            int id = tid + i * 256;
            int row = id >> 3, f = id & 7;
            unsigned h0, l0, h1, l1;
            cvt_pair(pb[i].x, pb[i].y, h0, l0);
            cvt_pair(pb[i].z, pb[i].w, h1, l1);
            Bh[row][f * 2] = h0; Bh[row][f * 2 + 1] = h1;
            Bl[row][f * 2] = l0; Bl[row][f * 2 + 1] = l1;
        }
        __syncthreads();

        if (k0 + 32 < K) {
            #pragma unroll
            for (int i = 0; i < 4; i++) {
                int id = tid + i * 256;
                int row = id >> 3, f = id & 7;
                pa[i] = *(const float4*)(A + (size_t)(row0 + row) * K + (k0 + 32) + f * 4);
            }
            #pragma unroll
            for (int i = 0; i < 2; i++) {
                int id = tid + i * 256;
                int row = id >> 3, f = id & 7;
                pb[i] = make_float4(0.f, 0.f, 0.f, 0.f);
                if (col0 + row < Ntot)
                    pb[i] = *(const float4*)(Bw + (size_t)(col0 + row) * K + (k0 + 32) + f * 4);
            }
        }

        #pragma unroll
        for (int kk = 0; kk < 2; kk++) {
            int kb = kk * 8 + (lane & 3);
            unsigned ah[2][4], al[2][4];
            #pragma unroll
            for (int mt = 0; mt < 2; mt++) {
                int ar = warpM * 32 + mt * 16 + (lane >> 2);
                ah[mt][0] = Ah[ar][kb];     ah[mt][1] = Ah[ar + 8][kb];
                ah[mt][2] = Ah[ar][kb + 4]; ah[mt][3] = Ah[ar + 8][kb + 4];
                al[mt][0] = Al[ar][kb];     al[mt][1] = Al[ar + 8][kb];
                al[mt][2] = Al[ar][kb + 4]; al[mt][3] = Al[ar + 8][kb + 4];
            }
            #pragma unroll
            for (int nt = 0; nt < 4; nt++) {
                int br = warpN * 32 + nt * 8 + (lane >> 2);
                unsigned bh0 = Bh[br][kb], bh1 = Bh[br][kb + 4];
                unsigned bl0 = Bl[br][kb], bl1 = Bl[br][kb + 4];
                #pragma unroll
                for (int mt = 0; mt < 2; mt++) {
                    mma_bf16(acc[mt][nt], ah[mt][0], ah[mt][1], ah[mt][2], ah[mt][3], bh0, bh1);
                    mma_bf16(acc[mt][nt], ah[mt][0], ah[mt][1], ah[mt][2], ah[mt][3], bl0, bl1);
                    mma_bf16(acc[mt][nt], al[mt][0], al[mt][1], al[mt][2], al[mt][3], bh0, bh1);
                }
            }
        }
        __syncthreads();
    }

    #pragma unroll
    for (int mt = 0; mt < 2; mt++) {
        #pragma unroll
        for (int nt = 0; nt < 4; nt++) {
            #pragma unroll
            for (int e = 0; e < 4; e++) {
                int p = row0 + warpM * 32 + mt * 16 + (lane >> 2) + ((e >= 2) ? 8 : 0);
                int o = col0 + warpN * 32 + nt * 8 + 2 * (lane & 3) + (e & 1);
                float v = acc[mt][nt][e];
                int bidx = p >> 12, hw = p & 4095;
                if (MODE == 0) {
                    if (o < 64) {
                        g_qbuf[p * 64 + o] = v;
                    } else if (o < 128) {
                        int c = o - 64;
                        g_kbufh[((size_t)(bidx * 2 + (c >> 5)) * HWP + hw) * GCC + (c & 31)] =
                            __float2half(v);
                    } else {
                        int c = o - 128;
                        g_vbufh[((size_t)(bidx * 2 + (c >> 5)) * HWP + hw) * GCC + (c & 31)] =
                            __float2half(v);
                    }
                } else if (MODE == 1) {
                    g_ybuf[(size_t)p * DIMC + o] =
                        v + bias[o] + resid[(size_t)bidx * DIMC * HWP + o * HWP + hw];
                } else {
                    if (o < Ntot)
                        outp[(size_t)bidx * NCLS * HWP + o * HWP + hw] = v + bias[o];
                }
            }
        }
    }
}

// ---------------- kernel 3: smem-tiled depthwise 3x3 + LN(32) + GELU ----------
__global__ void __launch_bounds__(256, 2) k_dw(const float* __restrict__ wdw,
                                               const float* __restrict__ g2,
                                               const float* __restrict__ b2)
{
    extern __shared__ float4 st4[];
    __shared__ float sw[GCC * 9];
    __shared__ float sg[GCC], sb[GCC];

    int bg = blockIdx.x >> 4;
    int h0 = (blockIdx.x & 15) * 4;
    int b = bg >> 1, g = bg & 1;
    int tid = threadIdx.x;

    for (int i = tid; i < GCC * 9; i += 256) sw[i] = wdw[i];
    if (tid < GCC) { sg[tid] = g2[tid]; sb[tid] = b2[tid]; }
    for (int i = tid; i < 3168; i += 256) st4[i] = make_float4(0.f, 0.f, 0.f, 0.f);
    __syncthreads();

    for (int i = tid; i < 3072; i += 256) {
        int c4 = i & 7, col = (i >> 3) & 63, r = i >> 9;
        int gr = h0 - 1 + r;
        if ((unsigned)gr < 64u)
            st4[(c4 * 6 + r) * 66 + col + 1] =
                *(const float4*)(g_qbuf + ((size_t)(b * HWP + gr * 64 + col)) * CRC + g * GCC + c4 * 4);
    }
    __syncthreads();

    int col = tid & 63;
    int row = tid >> 6;
    int h = h0 + row;

    float acc[GCC];
    #pragma unroll
    for (int c = 0; c < GCC; c++) acc[c] = 0.f;

    #pragma unroll
    for (int ky = 0; ky < 3; ky++) {
        #pragma unroll
        for (int kx = 0; kx < 3; kx++) {
            int kidx = ky * 3 + kx;
            #pragma unroll
            for (int c4 = 0; c4 < 8; c4++) {
                float4 v = st4[(c4 * 6 + row + ky) * 66 + col + kx];
                acc[c4 * 4 + 0] += v.x * sw[(c4 * 4 + 0) * 9 + kidx];
                acc[c4 * 4 + 1] += v.y * sw[(c4 * 4 + 1) * 9 + kidx];
                acc[c4 * 4 + 2] += v.z * sw[(c4 * 4 + 2) * 9 + kidx];
                acc[c4 * 4 + 3] += v.w * sw[(c4 * 4 + 3) * 9 + kidx];
            }
        }
    }

    float m = 0.f;
    #pragma unroll
    for (int c = 0; c < GCC; c++) m += acc[c];
    m *= (1.f / GCC);
    float v = 0.f;
    #pragma unroll
    for (int c = 0; c < GCC; c++) { float d = acc[c] - m; v += d * d; }
    float rs = rsqrtf(v * (1.f / GCC) + 1e-5f);

    float* dst = g_tbuf + ((size_t)bg * HWP + h * 64 + col) * GCC;
    #pragma unroll
    for (int c = 0; c < GCC; c++) {
        float t = (acc[c] - m) * rs * sg[c] + sb[c];
        dst[c] = 0.5f * t * (1.f + erff(t * 0.70710678118654752f));
    }
}

// ---------------- kernel 4: smem-tiled 3x3 conv (32->18), 2 rows/block --------
__global__ void __launch_bounds__(256) k_off(const float* __restrict__ woff,
                                             const float* __restrict__ boff,
                                             const float* __restrict__ offset)
{
    extern __shared__ float4 dyn4[];
    float4* st4 = dyn4;
    float*  sw  = (float*)(dyn4 + 2112);
    float4* sw4 = (float4*)sw;

    int bg = blockIdx.x >> 5;
    int h0 = (blockIdx.x & 31) * 2;
    int tid = threadIdx.x;

    for (int i = tid; i < OFFC * GCC * 9; i += 256) {
        int o = i / (GCC * 9); int rem = i - o * (GCC * 9);
        int c = rem / 9; int kidx = rem - c * 9;
        sw[(kidx * OFFC + o) * GCC + c] = woff[i];
    }
    for (int i = tid; i < 2112; i += 256) st4[i] = make_float4(0.f, 0.f, 0.f, 0.f);
    __syncthreads();

    for (int i = tid; i < 2048; i += 256) {
        int c4 = i & 7, col = (i >> 3) & 63, r = i >> 9;
        int gr = h0 - 1 + r;
        if ((unsigned)gr < 64u)
            st4[(c4 * 4 + r) * 66 + col + 1] =
                *(const float4*)(g_tbuf + ((size_t)(bg * HWP + gr * 64 + col)) * GCC + c4 * 4);
    }
    __syncthreads();

    int col = tid & 63;
    int og  = (tid >> 6) & 1;
    int row = tid >> 7;
    int h = h0 + row;
    int b = bg >> 1;

    float acc[9];
    #pragma unroll
    for (int o = 0; o < 9; o++) acc[o] = boff[og * 9 + o];

    #pragma unroll
    for (int c4 = 0; c4 < 8; c4++) {
        #pragma unroll
        for (int ky = 0; ky < 3; ky++) {
            const float4* trow = &st4[(c4 * 4 + row + ky) * 66];
            float4 t[3];
            t[0] = trow[col]; t[1] = trow[col + 1]; t[2] = trow[col + 2];
            #pragma unroll
            for (int kx = 0; kx < 3; kx++) {
                int kidx = ky * 3 + kx;
                #pragma unroll
                for (int o = 0; o < 9; o++) {
                    float4 w = sw4[(kidx * OFFC + og * 9 + o) * 8 + c4];
                    acc[o] += t[kx].x * w.x + t[kx].y * w.y +
                              t[kx].z * w.z + t[kx].w * w.w;
                }
            }
        }
    }

    int hw = h * 64 + col;
    const float* ofs = offset + (size_t)b * OFFC * HWP + hw;
    float* dst = g_offbuf + ((size_t)bg * HWP + hw) * OFFC + og * 9;
    #pragma unroll
    for (int o = 0; o < 9; o++)
        dst[o] = tanhf(acc[o]) * MULF + ofs[(og * 9 + o) * HWP];
}

// ---------------- kernel 5: deformable gather + softmax attention (fp16 k/v) ---
__device__ __forceinline__ void samp16h(const __half* __restrict__ bufh,
                                        int y, int x, float w, float s[16])
{
    if ((unsigned)x < 64u && (unsigned)y < 64u) {
        const uint4* q = (const uint4*)(bufh + (y * 64 + x) * GCC);
        uint4 u0 = q[0], u1 = q[1];
        const __half2* h0 = (const __half2*)&u0;
        const __half2* h1 = (const __half2*)&u1;
        #pragma unroll
        for (int i = 0; i < 4; i++) {
            float2 f = __half22float2(h0[i]);
            s[2 * i]     += w * f.x;
            s[2 * i + 1] += w * f.y;
        }
        #pragma unroll
        for (int i = 0; i < 4; i++) {
            float2 f = __half22float2(h1[i]);
            s[8 + 2 * i]     += w * f.x;
            s[8 + 2 * i + 1] += w * f.y;
        }
    }
}

__global__ void k_attn(const float* __restrict__ rpb)
{
    int idx = blockIdx.x * blockDim.x + threadIdx.x;
    int nh = idx & 3;
    int p  = idx >> 2;
    int b = p >> 12, hw = p & 4095;
    int g = nh >> 1, hb = (nh & 1) * 16;
    int bg = b * 2 + g;

    float q[16];
    const float* qp = g_qbuf + (size_t)p * CRC + nh * HCC;
    #pragma unroll
    for (int i = 0; i < 16; i++) q[i] = qp[i] * SCALEF;

    const float* off = g_offbuf + (size_t)(bg * HWP + hw) * OFFC;
    const __half* kb = g_kbufh + (size_t)bg * HWP * GCC + hb;
    const __half* vb = g_vbufh + (size_t)bg * HWP * GCC + hb;
    const float* rp = rpb + nh * (N9 * HCC);

    int ix[N9], iy[N9];
    float fx[N9], fy[N9], logit[N9];

    #pragma unroll
    for (int n = 0; n < N9; n++) {
        float row = off[2 * n], col = off[2 * n + 1];
        float xf = floorf(col), yf = floorf(row);
        ix[n] = (int)xf; iy[n] = (int)yf;
        fx[n] = col - xf; fy[n] = row - yf;

        float w00 = (1.f - fx[n]) * (1.f - fy[n]);
        float w10 = fx[n] * (1.f - fy[n]);
        float w01 = (1.f - fx[n]) * fy[n];
        float w11 = fx[n] * fy[n];

        float s[16];
        #pragma unroll
        for (int i = 0; i < 16; i++) s[i] = 0.f;
        samp16h(kb, iy[n],     ix[n],     w00, s);
        samp16h(kb, iy[n],     ix[n] + 1, w10, s);
        samp16h(kb, iy[n] + 1, ix[n],     w01, s);
        samp16h(kb, iy[n] + 1, ix[n] + 1, w11, s);

        float l = 0.f;
        const float* rpn = rp + n * HCC;
        #pragma unroll
        for (int i = 0; i < 16; i++) l += q[i] * (s[i] + rpn[i]);
        logit[n] = l;
    }

    float mx = logit[0];
    #pragma unroll
    for (int n = 1; n < N9; n++) mx = fmaxf(mx, logit[n]);
    float sum = 0.f;
    #pragma unroll
    for (int n = 0; n < N9; n++) { logit[n] = __expf(logit[n] - mx); sum += logit[n]; }
    float inv = 1.f / sum;

    float o16[16];
    #pragma unroll
    for (int i = 0; i < 16; i++) o16[i] = 0.f;

    #pragma unroll
    for (int n = 0; n < N9; n++) {
        float wn = logit[n] * inv;
        float w00 = (1.f - fx[n]) * (1.f - fy[n]) * wn;
        float w10 = fx[n] * (1.f - fy[n]) * wn;
        float w01 = (1.f - fx[n]) * fy[n] * wn;
        float w11 = fx[n] * fy[n] * wn;
        samp16h(vb, iy[n],     ix[n],     w00, o16);
        samp16h(vb, iy[n],     ix[n] + 1, w10, o16);
        samp16h(vb, iy[n] + 1, ix[n],     w01, o16);
        samp16h(vb, iy[n] + 1, ix[n] + 1, w11, o16);
    }

    float* dst = g_attnout + (size_t)p * CRC + nh * HCC;
    #pragma unroll
    for (int i = 0; i < 16; i++) dst[i] = o16[i];
}

// ---------------- launch ----------------
extern "C" void kernel_launch(void* const* d_in, const int* in_sizes, int n_in,
                              void* d_out, int out_size)
{
    const float* x      = (const float*)d_in[0];
    const float* offset = (const float*)d_in[1];
    const float* ln1_g  = (const float*)d_in[2];
    const float* ln1_b  = (const float*)d_in[3];
    const float* w_qkv  = (const float*)d_in[4];
    const float* w_dw   = (const float*)d_in[5];
    const float* ln2_g  = (const float*)d_in[6];
    const float* ln2_b  = (const float*)d_in[7];
    const float* w_off  = (const float*)d_in[8];
    const float* b_off  = (const float*)d_in[9];
    const float* rpb    = (const float*)d_in[10];
    const float* w_proj = (const float*)d_in[11];
    const float* b_proj = (const float*)d_in[12];
    const float* w_cls  = (const float*)d_in[13];
    const float* b_cls  = (const float*)d_in[14];
    float* out = (float*)d_out;

    const int dwSmem  = 3168 * 16;
    const int offSmem = 2112 * 16 + 5184 * 4;
    static int configured = 0;
    if (!configured) {
        cudaFuncSetAttribute(k_dw,  cudaFuncAttributeMaxDynamicSharedMemorySize, dwSmem);
        cudaFuncSetAttribute(k_off, cudaFuncAttributeMaxDynamicSharedMemorySize, offSmem);
        configured = 1;
    }

    k_ln<<<PP / 32, 256>>>(x, ln1_g, ln1_b);
    k_gemm<0><<<dim3(3, PP / 128), 256>>>(w_qkv, nullptr, nullptr, nullptr);
    k_dw<<<16 * 16, 256, dwSmem>>>(w_dw, ln2_g, ln2_b);
    k_off<<<16 * 32, 256, offSmem>>>(w_off, b_off, offset);
    k_attn<<<(PP * 4) / 128, 128>>>(rpb);
    k_gemm<1><<<dim3(4, PP / 128), 256>>>(w_proj, b_proj, x, nullptr);
    k_gemm<2><<<dim3(2, PP / 128), 256>>>(w_cls, b_cls, nullptr, out);
}

// round 14
// speedup vs baseline: 1.1127x; 1.0557x over previous
#include <cuda_runtime.h>
#include <cuda_bf16.h>
#include <cuda_fp16.h>
#include <math.h>

// ---------------- static config ----------------
#define HWP   4096
#define PP    32768
#define DIMC  256
#define CRC   64
#define GCC   32
#define HCC   16
#define N9    9
#define OFFC  18
#define NCLS  80
#define SCALEF 0.25f
#define MULF  5.0f

// ---------------- scratch ----------------
__device__ float  g_xn[PP * DIMC];
__device__ float  g_qbuf[PP * CRC];
__device__ __half g_kbufh[16 * HWP * GCC];
__device__ __half g_vbufh[16 * HWP * GCC];
__device__ float  g_tbuf[16 * HWP * GCC];
__device__ float  g_offbuf[16 * HWP * OFFC];
__device__ float  g_attnout[PP * CRC];

// ---------------- kernel 1: channel-LN + NCHW -> [P,C] transpose ----------------
__global__ void k_ln(const float* __restrict__ x,
                     const float* __restrict__ gam,
                     const float* __restrict__ bet)
{
    __shared__ float s[DIMC][33];
    __shared__ float red[2][8][32];
    __shared__ float smean[32], srstd[32];

    int p0 = blockIdx.x * 32;
    int b  = p0 >> 12;
    int hw0 = p0 & 4095;
    int tid = threadIdx.x;
    int tx = tid & 31, ty = tid >> 5;

    const float* xb = x + (size_t)b * DIMC * HWP + hw0;
    for (int c = ty; c < DIMC; c += 8)
        s[c][tx] = xb[c * HWP + tx];
    __syncthreads();

    float sum = 0.f, sq = 0.f;
    for (int c = ty; c < DIMC; c += 8) {
        float v = s[c][tx];
        sum += v; sq += v * v;
    }
    red[0][ty][tx] = sum; red[1][ty][tx] = sq;
    __syncthreads();
    if (ty == 0) {
        float s1 = 0.f, s2 = 0.f;
        #pragma unroll
        for (int j = 0; j < 8; j++) { s1 += red[0][j][tx]; s2 += red[1][j][tx]; }
        float m = s1 * (1.f / 256.f);
        float v = s2 * (1.f / 256.f) - m * m;
        smean[tx] = m;
        srstd[tx] = rsqrtf(v + 1e-5f);
    }
    __syncthreads();

    float gg = gam[tid], bb = bet[tid];
    for (int pl = 0; pl < 32; pl++) {
        g_xn[(size_t)(p0 + pl) * DIMC + tid] =
            (s[tid][pl] - smean[pl]) * srstd[pl] * gg + bb;
    }
}

// ---------------- helpers: bf16 split + mma ----------------
__device__ __forceinline__ void cvt_pair(float x0, float x1,
                                         unsigned& hi, unsigned& lo)
{
    __nv_bfloat16 h0 = __float2bfloat16(x0);
    __nv_bfloat16 h1 = __float2bfloat16(x1);
    float r0 = x0 - __bfloat162float(h0);
    float r1 = x1 - __bfloat162float(h1);
    __nv_bfloat16 l0 = __float2bfloat16(r0);
    __nv_bfloat16 l1 = __float2bfloat16(r1);
    unsigned short u0 = *(unsigned short*)&h0, u1 = *(unsigned short*)&h1;
    unsigned short v0 = *(unsigned short*)&l0, v1 = *(unsigned short*)&l1;
    hi = (unsigned)u0 | ((unsigned)u1 << 16);
    lo = (unsigned)v0 | ((unsigned)v1 << 16);
}

__device__ __forceinline__ void mma_bf16(float* c,
                                         unsigned a0, unsigned a1, unsigned a2, unsigned a3,
                                         unsigned b0, unsigned b1)
{
    asm volatile(
        "mma.sync.aligned.m16n8k16.row.col.f32.bf16.bf16.f32 "
        "{%0,%1,%2,%3}, {%4,%5,%6,%7}, {%8,%9}, {%0,%1,%2,%3};\n"
        : "+f"(c[0]), "+f"(c[1]), "+f"(c[2]), "+f"(c[3])
        : "r"(a0), "r"(a1), "r"(a2), "r"(a3), "r"(b0), "r"(b1));
}

// ---------------- GEMM 0 (qkv) — mma.sync, reg prefetch (R12 best) ------------
__global__ void __launch_bounds__(256) k_gemm0(const float* __restrict__ Bw)
{
    constexpr int K = 256, Ntot = 192;
    const float* A = g_xn;

    __shared__ unsigned Ah[128][20], Al[128][20];
    __shared__ unsigned Bh[64][20],  Bl[64][20];

    int tid = threadIdx.x;
    int lane = tid & 31;
    int warpId = tid >> 5;
    int warpM = warpId & 3;
    int warpN = warpId >> 2;
    int row0 = blockIdx.y * 128, col0 = blockIdx.x * 64;

    float acc[2][4][4];
    #pragma unroll
    for (int mt = 0; mt < 2; mt++)
        #pragma unroll
        for (int nt = 0; nt < 4; nt++)
            #pragma unroll
            for (int e = 0; e < 4; e++) acc[mt][nt][e] = 0.f;

    float4 pa[4], pb[2];
    #pragma unroll
    for (int i = 0; i < 4; i++) {
        int id = tid + i * 256;
        int row = id >> 3, f = id & 7;
        pa[i] = *(const float4*)(A + (size_t)(row0 + row) * K + f * 4);
    }
    #pragma unroll
    for (int i = 0; i < 2; i++) {
        int id = tid + i * 256;
        int row = id >> 3, f = id & 7;
        pb[i] = make_float4(0.f, 0.f, 0.f, 0.f);
        if (col0 + row < Ntot)
            pb[i] = *(const float4*)(Bw + (size_t)(col0 + row) * K + f * 4);
    }

    for (int k0 = 0; k0 < K; k0 += 32) {
        #pragma unroll
        for (int i = 0; i < 4; i++) {
            int id = tid + i * 256;
            int row = id >> 3, f = id & 7;
            unsigned h0, l0, h1, l1;
            cvt_pair(pa[i].x, pa[i].y, h0, l0);
            cvt_pair(pa[i].z, pa[i].w, h1, l1);
            Ah[row][f * 2] = h0; Ah[row][f * 2 + 1] = h1;
            Al[row][f * 2] = l0; Al[row][f * 2 + 1] = l1;
        }
        #pragma unroll
        for (int i = 0; i < 2; i++) {
            int id = tid + i * 256;
            int row = id >> 3, f = id & 7;
            unsigned h0, l0, h1, l1;
            cvt_pair(pb[i].x, pb[i].y, h0, l0);
            cvt_pair(pb[i].z, pb[i].w, h1, l1);
            Bh[row][f * 2] = h0; Bh[row][f * 2 + 1] = h1;
            Bl[row][f * 2] = l0; Bl[row][f * 2 + 1] = l1;
        }
        __syncthreads();

        if (k0 + 32 < K) {
            #pragma unroll
            for (int i = 0; i < 4; i++) {
                int id = tid + i * 256;
                int row = id >> 3, f = id & 7;
                pa[i] = *(const float4*)(A + (size_t)(row0 + row) * K + (k0 + 32) + f * 4);
            }
            #pragma unroll
            for (int i = 0; i < 2; i++) {
                int id = tid + i * 256;
                int row = id >> 3, f = id & 7;
                pb[i] = make_float4(0.f, 0.f, 0.f, 0.f);
                if (col0 + row < Ntot)
                    pb[i] = *(const float4*)(Bw + (size_t)(col0 + row) * K + (k0 + 32) + f * 4);
            }
        }

        #pragma unroll
        for (int kk = 0; kk < 2; kk++) {
            int kb = kk * 8 + (lane & 3);
            unsigned ah[2][4], al[2][4];
            #pragma unroll
            for (int mt = 0; mt < 2; mt++) {
                int ar = warpM * 32 + mt * 16 + (lane >> 2);
                ah[mt][0] = Ah[ar][kb];     ah[mt][1] = Ah[ar + 8][kb];
                ah[mt][2] = Ah[ar][kb + 4]; ah[mt][3] = Ah[ar + 8][kb + 4];
                al[mt][0] = Al[ar][kb];     al[mt][1] = Al[ar + 8][kb];
                al[mt][2] = Al[ar][kb + 4]; al[mt][3] = Al[ar + 8][kb + 4];
            }
            #pragma unroll
            for (int nt = 0; nt < 4; nt++) {
                int br = warpN * 32 + nt * 8 + (lane >> 2);
                unsigned bh0 = Bh[br][kb], bh1 = Bh[br][kb + 4];
                unsigned bl0 = Bl[br][kb], bl1 = Bl[br][kb + 4];
                #pragma unroll
                for (int mt = 0; mt < 2; mt++) {
                    mma_bf16(acc[mt][nt], ah[mt][0], ah[mt][1], ah[mt][2], ah[mt][3], bh0, bh1);
                    mma_bf16(acc[mt][nt], ah[mt][0], ah[mt][1], ah[mt][2], ah[mt][3], bl0, bl1);
                    mma_bf16(acc[mt][nt], al[mt][0], al[mt][1], al[mt][2], al[mt][3], bh0, bh1);
                }
            }
        }
        __syncthreads();
    }

    #pragma unroll
    for (int mt = 0; mt < 2; mt++) {
        #pragma unroll
        for (int nt = 0; nt < 4; nt++) {
            #pragma unroll
            for (int e = 0; e < 4; e++) {
                int p = row0 + warpM * 32 + mt * 16 + (lane >> 2) + ((e >= 2) ? 8 : 0);
                int o = col0 + warpN * 32 + nt * 8 + 2 * (lane & 3) + (e & 1);
                float v = acc[mt][nt][e];
                int bidx = p >> 12, hw = p & 4095;
                if (o < 64) {
                    g_qbuf[p * 64 + o] = v;
                } else if (o < 128) {
                    int c = o - 64;
                    g_kbufh[((size_t)(bidx * 2 + (c >> 5)) * HWP + hw) * GCC + (c & 31)] =
                        __float2half(v);
                } else {
                    int c = o - 128;
                    g_vbufh[((size_t)(bidx * 2 + (c >> 5)) * HWP + hw) * GCC + (c & 31)] =
                        __float2half(v);
                }
            }
        }
    }
}

// ---------------- fused proj + residual + cls -------------------------------
// Block = 64 pixels, 256 threads (8 warps: warpM in {0,1}, warpN in {0..3}).
// Phase 1: y[64,256] = attnout[64,64] @ w_proj^T + b_proj + x  -> smem bf16 hi/lo
// Phase 2: out[64,80] = y @ w_cls^T + b_cls                      (A from smem)
// smem layout (unsigned units): yh[64*130], yl[64*130], Bh[128*20], Bl[128*20],
//                               Ah[64*20], Al[64*20]  -> 24320 u = 97280 B
__global__ void __launch_bounds__(256) k_projcls(const float* __restrict__ w_proj,
                                                 const float* __restrict__ b_proj,
                                                 const float* __restrict__ xres,
                                                 const float* __restrict__ w_cls,
                                                 const float* __restrict__ b_cls,
                                                 float* __restrict__ outp)
{
    extern __shared__ unsigned sm[];
    unsigned* yh = sm;
    unsigned* yl = sm + 8320;
    unsigned* Bh = sm + 16640;
    unsigned* Bl = sm + 19200;
    unsigned* Ah = sm + 21760;
    unsigned* Al = sm + 23040;

    int tid = threadIdx.x;
    int lane = tid & 31;
    int warpId = tid >> 5;
    int warpM = warpId & 1;          // 2 x 32 rows
    int warpN = warpId >> 1;         // 4
    int row0 = blockIdx.x * 64;
    int bidx = row0 >> 12;

    // ================= phase 1: proj =================
    for (int nc = 0; nc < 2; nc++) {
        float acc[2][4][4];
        #pragma unroll
        for (int mt = 0; mt < 2; mt++)
            #pragma unroll
            for (int nt = 0; nt < 4; nt++)
                #pragma unroll
                for (int e = 0; e < 4; e++) acc[mt][nt][e] = 0.f;

        for (int k0 = 0; k0 < 64; k0 += 32) {
            // stage A (attnout 64 x 32): 512 float4, 2 per thread
            #pragma unroll
            for (int i = 0; i < 2; i++) {
                int u = tid + i * 256;
                int row = u >> 3, f = u & 7;
                float4 v = *(const float4*)(g_attnout + (size_t)(row0 + row) * CRC + k0 + f * 4);
                unsigned h0, l0, h1, l1;
                cvt_pair(v.x, v.y, h0, l0);
                cvt_pair(v.z, v.w, h1, l1);
                Ah[row * 20 + f * 2] = h0; Ah[row * 20 + f * 2 + 1] = h1;
                Al[row * 20 + f * 2] = l0; Al[row * 20 + f * 2 + 1] = l1;
            }
            // stage B (w_proj rows nc*128..+127 x 32k): 1024 float4, 4/thread
            #pragma unroll
            for (int i = 0; i < 4; i++) {
                int u = tid + i * 256;
                int row = u >> 3, f = u & 7;
                float4 v = *(const float4*)(w_proj + (size_t)(nc * 128 + row) * CRC + k0 + f * 4);
                unsigned h0, l0, h1, l1;
                cvt_pair(v.x, v.y, h0, l0);
                cvt_pair(v.z, v.w, h1, l1);
                Bh[row * 20 + f * 2] = h0; Bh[row * 20 + f * 2 + 1] = h1;
                Bl[row * 20 + f * 2] = l0; Bl[row * 20 + f * 2 + 1] = l1;
            }
            __syncthreads();

            #pragma unroll
            for (int kk = 0; kk < 2; kk++) {
                int kb = kk * 8 + (lane & 3);
                unsigned ah[2][4], al[2][4];
                #pragma unroll
                for (int mt = 0; mt < 2; mt++) {
                    int ar = warpM * 32 + mt * 16 + (lane >> 2);
                    ah[mt][0] = Ah[ar * 20 + kb];       ah[mt][1] = Ah[(ar + 8) * 20 + kb];
                    ah[mt][2] = Ah[ar * 20 + kb + 4];   ah[mt][3] = Ah[(ar + 8) * 20 + kb + 4];
                    al[mt][0] = Al[ar * 20 + kb];       al[mt][1] = Al[(ar + 8) * 20 + kb];
                    al[mt][2] = Al[ar * 20 + kb + 4];   al[mt][3] = Al[(ar + 8) * 20 + kb + 4];
                }
                #pragma unroll
                for (int nt = 0; nt < 4; nt++) {
                    int br = warpN * 32 + nt * 8 + (lane >> 2);
                    unsigned bh0 = Bh[br * 20 + kb], bh1 = Bh[br * 20 + kb + 4];
                    unsigned bl0 = Bl[br * 20 + kb], bl1 = Bl[br * 20 + kb + 4];
                    #pragma unroll
                    for (int mt = 0; mt < 2; mt++) {
                        mma_bf16(acc[mt][nt], ah[mt][0], ah[mt][1], ah[mt][2], ah[mt][3], bh0, bh1);
                        mma_bf16(acc[mt][nt], ah[mt][0], ah[mt][1], ah[mt][2], ah[mt][3], bl0, bl1);
                        mma_bf16(acc[mt][nt], al[mt][0], al[mt][1], al[mt][2], al[mt][3], bh0, bh1);
                    }
                }
            }
            __syncthreads();
        }

        // epilogue nc: bias + residual, split to bf16, store to y smem
        #pragma unroll
        for (int mt = 0; mt < 2; mt++) {
            #pragma unroll
            for (int nt = 0; nt < 4; nt++) {
                #pragma unroll
                for (int ep = 0; ep < 2; ep++) {
                    int r = warpM * 32 + mt * 16 + (lane >> 2) + ep * 8;
                    int p = row0 + r;
                    int hw = p & 4095;
                    int o0 = nc * 128 + warpN * 32 + nt * 8 + 2 * (lane & 3);
                    float v0 = acc[mt][nt][ep * 2] + b_proj[o0]
                             + xres[(size_t)bidx * DIMC * HWP + (size_t)o0 * HWP + hw];
                    float v1 = acc[mt][nt][ep * 2 + 1] + b_proj[o0 + 1]
                             + xres[(size_t)bidx * DIMC * HWP + (size_t)(o0 + 1) * HWP + hw];
                    unsigned hi, lo;
                    cvt_pair(v0, v1, hi, lo);
                    yh[r * 130 + (o0 >> 1)] = hi;
                    yl[r * 130 + (o0 >> 1)] = lo;
                }
            }
        }
        __syncthreads();
    }

    // ================= phase 2: cls (N padded 80->96, warp tile 32x24) ========
    float acc2[2][3][4];
    #pragma unroll
    for (int mt = 0; mt < 2; mt++)
        #pragma unroll
        for (int nt = 0; nt < 3; nt++)
            #pragma unroll
            for (int e = 0; e < 4; e++) acc2[mt][nt][e] = 0.f;

    for (int kc = 0; kc < 8; kc++) {
        // stage w_cls chunk: 96 rows x 32 k (rows >= 80 zero): 768 float4, 3/thread
        #pragma unroll
        for (int i = 0; i < 3; i++) {
            int u = tid + i * 256;
            int row = u >> 3, f = u & 7;
            float4 v = make_float4(0.f, 0.f, 0.f, 0.f);
            if (row < NCLS)
                v = *(const float4*)(w_cls + (size_t)row * DIMC + kc * 32 + f * 4);
            unsigned h0, l0, h1, l1;
            cvt_pair(v.x, v.y, h0, l0);
            cvt_pair(v.z, v.w, h1, l1);
            Bh[row * 20 + f * 2] = h0; Bh[row * 20 + f * 2 + 1] = h1;
            Bl[row * 20 + f * 2] = l0; Bl[row * 20 + f * 2 + 1] = l1;
        }
        __syncthreads();

        int kbase = kc * 16;
        #pragma unroll
        for (int kk = 0; kk < 2; kk++) {
            int kb = kk * 8 + (lane & 3);
            unsigned ah[2][4], al[2][4];
            #pragma unroll
            for (int mt = 0; mt < 2; mt++) {
                int ar = warpM * 32 + mt * 16 + (lane >> 2);
                ah[mt][0] = yh[ar * 130 + kbase + kb];
                ah[mt][1] = yh[(ar + 8) * 130 + kbase + kb];
                ah[mt][2] = yh[ar * 130 + kbase + kb + 4];
                ah[mt][3] = yh[(ar + 8) * 130 + kbase + kb + 4];
                al[mt][0] = yl[ar * 130 + kbase + kb];
                al[mt][1] = yl[(ar + 8) * 130 + kbase + kb];
                al[mt][2] = yl[ar * 130 + kbase + kb + 4];
                al[mt][3] = yl[(ar + 8) * 130 + kbase + kb + 4];
            }
            #pragma unroll
            for (int nt = 0; nt < 3; nt++) {
                int br = warpN * 24 + nt * 8 + (lane >> 2);
                unsigned bh0 = Bh[br * 20 + kb], bh1 = Bh[br * 20 + kb + 4];
                unsigned bl0 = Bl[br * 20 + kb], bl1 = Bl[br * 20 + kb + 4];
                #pragma unroll
                for (int mt = 0; mt < 2; mt++) {
                    mma_bf16(acc2[mt][nt], ah[mt][0], ah[mt][1], ah[mt][2], ah[mt][3], bh0, bh1);
                    mma_bf16(acc2[mt][nt], ah[mt][0], ah[mt][1], ah[mt][2], ah[mt][3], bl0, bl1);
                    mma_bf16(acc2[mt][nt], al[mt][0], al[mt][1], al[mt][2], al[mt][3], bh0, bh1);
                }
            }
        }
        __syncthreads();
    }

    #pragma unroll
    for (int mt = 0; mt < 2; mt++) {
        #pragma unroll
        for (int nt = 0; nt < 3; nt++) {
            #pragma unroll
            for (int e = 0; e < 4; e++) {
                int p = row0 + warpM * 32 + mt * 16 + (lane >> 2) + ((e >= 2) ? 8 : 0);
                int o = warpN * 24 + nt * 8 + 2 * (lane & 3) + (e & 1);
                int hw = p & 4095;
                if (o < NCLS)
                    outp[(size_t)bidx * NCLS * HWP + (size_t)o * HWP + hw] =
                        acc2[mt][nt][e] + b_cls[o];
            }
        }
    }
}

// ---------------- kernel 3: smem-tiled depthwise 3x3 + LN(32) + GELU ----------
__global__ void __launch_bounds__(256, 2) k_dw(const float* __restrict__ wdw,
                                               const float* __restrict__ g2,
                                               const float* __restrict__ b2)
{
    extern __shared__ float4 st4[];
    __shared__ float sw[GCC * 9];
    __shared__ float sg[GCC], sb[GCC];

    int bg = blockIdx.x >> 4;
    int h0 = (blockIdx.x & 15) * 4;
    int b = bg >> 1, g = bg & 1;
    int tid = threadIdx.x;

    for (int i = tid; i < GCC * 9; i += 256) sw[i] = wdw[i];
    if (tid < GCC) { sg[tid] = g2[tid]; sb[tid] = b2[tid]; }
    for (int i = tid; i < 3168; i += 256) st4[i] = make_float4(0.f, 0.f, 0.f, 0.f);
    __syncthreads();

    for (int i = tid; i < 3072; i += 256) {
        int c4 = i & 7, col = (i >> 3) & 63, r = i >> 9;
        int gr = h0 - 1 + r;
        if ((unsigned)gr < 64u)
            st4[(c4 * 6 + r) * 66 + col + 1] =
                *(const float4*)(g_qbuf + ((size_t)(b * HWP + gr * 64 + col)) * CRC + g * GCC + c4 * 4);
    }
    __syncthreads();

    int col = tid & 63;
    int row = tid >> 6;
    int h = h0 + row;

    float acc[GCC];
    #pragma unroll
    for (int c = 0; c < GCC; c++) acc[c] = 0.f;

    #pragma unroll
    for (int ky = 0; ky < 3; ky++) {
        #pragma unroll
        for (int kx = 0; kx < 3; kx++) {
            int kidx = ky * 3 + kx;
            #pragma unroll
            for (int c4 = 0; c4 < 8; c4++) {
                float4 v = st4[(c4 * 6 + row + ky) * 66 + col + kx];
                acc[c4 * 4 + 0] += v.x * sw[(c4 * 4 + 0) * 9 + kidx];
                acc[c4 * 4 + 1] += v.y * sw[(c4 * 4 + 1) * 9 + kidx];
                acc[c4 * 4 + 2] += v.z * sw[(c4 * 4 + 2) * 9 + kidx];
                acc[c4 * 4 + 3] += v.w * sw[(c4 * 4 + 3) * 9 + kidx];
            }
        }
    }

    float m = 0.f;
    #pragma unroll
    for (int c = 0; c < GCC; c++) m += acc[c];
    m *= (1.f / GCC);
    float v = 0.f;
    #pragma unroll
    for (int c = 0; c < GCC; c++) { float d = acc[c] - m; v += d * d; }
    float rs = rsqrtf(v * (1.f / GCC) + 1e-5f);

    float* dst = g_tbuf + ((size_t)bg * HWP + h * 64 + col) * GCC;
    #pragma unroll
    for (int c = 0; c < GCC; c++) {
        float t = (acc[c] - m) * rs * sg[c] + sb[c];
        dst[c] = 0.5f * t * (1.f + erff(t * 0.70710678118654752f));
    }
}

// ---------------- kernel 4: smem-tiled 3x3 conv (32->18), 2 rows/block --------
__global__ void __launch_bounds__(256) k_off(const float* __restrict__ woff,
                                             const float* __restrict__ boff,
                                             const float* __restrict__ offset)
{
    extern __shared__ float4 dyn4[];
    float4* st4 = dyn4;
    float*  sw  = (float*)(dyn4 + 2112);
    float4* sw4 = (float4*)sw;

    int bg = blockIdx.x >> 5;
    int h0 = (blockIdx.x & 31) * 2;
    int tid = threadIdx.x;

    for (int i = tid; i < OFFC * GCC * 9; i += 256) {
        int o = i / (GCC * 9); int rem = i - o * (GCC * 9);
        int c = rem / 9; int kidx = rem - c * 9;
        sw[(kidx * OFFC + o) * GCC + c] = woff[i];
    }
    for (int i = tid; i < 2112; i += 256) st4[i] = make_float4(0.f, 0.f, 0.f, 0.f);
    __syncthreads();

    for (int i = tid; i < 2048; i += 256) {
        int c4 = i & 7, col = (i >> 3) & 63, r = i >> 9;
        int gr = h0 - 1 + r;
        if ((unsigned)gr < 64u)
            st4[(c4 * 4 + r) * 66 + col + 1] =
                *(const float4*)(g_tbuf + ((size_t)(bg * HWP + gr * 64 + col)) * GCC + c4 * 4);
    }
    __syncthreads();

    int col = tid & 63;
    int og  = (tid >> 6) & 1;
    int row = tid >> 7;
    int h = h0 + row;
    int b = bg >> 1;

    float acc[9];
    #pragma unroll
    for (int o = 0; o < 9; o++) acc[o] = boff[og * 9 + o];

    #pragma unroll
    for (int c4 = 0; c4 < 8; c4++) {
        #pragma unroll
        for (int ky = 0; ky < 3; ky++) {
            const float4* trow = &st4[(c4 * 4 + row + ky) * 66];
            float4 t[3];
            t[0] = trow[col]; t[1] = trow[col + 1]; t[2] = trow[col + 2];
            #pragma unroll
            for (int kx = 0; kx < 3; kx++) {
                int kidx = ky * 3 + kx;
                #pragma unroll
                for (int o = 0; o < 9; o++) {
                    float4 w = sw4[(kidx * OFFC + og * 9 + o) * 8 + c4];
                    acc[o] += t[kx].x * w.x + t[kx].y * w.y +
                              t[kx].z * w.z + t[kx].w * w.w;
                }
            }
        }
    }

    int hw = h * 64 + col;
    const float* ofs = offset + (size_t)b * OFFC * HWP + hw;
    float* dst = g_offbuf + ((size_t)bg * HWP + hw) * OFFC + og * 9;
    #pragma unroll
    for (int o = 0; o < 9; o++)
        dst[o] = tanhf(acc[o]) * MULF + ofs[(og * 9 + o) * HWP];
}

// ---------------- kernel 5: deformable gather + softmax attention (fp16 k/v) ---
__device__ __forceinline__ void samp16h(const __half* __restrict__ bufh,
                                        int y, int x, float w, float s[16])
{
    if ((unsigned)x < 64u && (unsigned)y < 64u) {
        const uint4* q = (const uint4*)(bufh + (y * 64 + x) * GCC);
        uint4 u0 = q[0], u1 = q[1];
        const __half2* h0 = (const __half2*)&u0;
        const __half2* h1 = (const __half2*)&u1;
        #pragma unroll
        for (int i = 0; i < 4; i++) {
            float2 f = __half22float2(h0[i]);
            s[2 * i]     += w * f.x;
            s[2 * i + 1] += w * f.y;
        }
        #pragma unroll
        for (int i = 0; i < 4; i++) {
            float2 f = __half22float2(h1[i]);
            s[8 + 2 * i]     += w * f.x;
            s[8 + 2 * i + 1] += w * f.y;
        }
    }
}

__global__ void k_attn(const float* __restrict__ rpb)
{
    int idx = blockIdx.x * blockDim.x + threadIdx.x;
    int nh = idx & 3;
    int p  = idx >> 2;
    int b = p >> 12, hw = p & 4095;
    int g = nh >> 1, hb = (nh & 1) * 16;
    int bg = b * 2 + g;

    float q[16];
    const float* qp = g_qbuf + (size_t)p * CRC + nh * HCC;
    #pragma unroll
    for (int i = 0; i < 16; i++) q[i] = qp[i] * SCALEF;

    const float* off = g_offbuf + (size_t)(bg * HWP + hw) * OFFC;
    const __half* kb = g_kbufh + (size_t)bg * HWP * GCC + hb;
    const __half* vb = g_vbufh + (size_t)bg * HWP * GCC + hb;
    const float* rp = rpb + nh * (N9 * HCC);

    int ix[N9], iy[N9];
    float fx[N9], fy[N9], logit[N9];

    #pragma unroll
    for (int n = 0; n < N9; n++) {
        float row = off[2 * n], col = off[2 * n + 1];
        float xf = floorf(col), yf = floorf(row);
        ix[n] = (int)xf; iy[n] = (int)yf;
        fx[n] = col - xf; fy[n] = row - yf;

        float w00 = (1.f - fx[n]) * (1.f - fy[n]);
        float w10 = fx[n] * (1.f - fy[n]);
        float w01 = (1.f - fx[n]) * fy[n];
        float w11 = fx[n] * fy[n];

        float s[16];
        #pragma unroll
        for (int i = 0; i < 16; i++) s[i] = 0.f;
        samp16h(kb, iy[n],     ix[n],     w00, s);
        samp16h(kb, iy[n],     ix[n] + 1, w10, s);
        samp16h(kb, iy[n] + 1, ix[n],     w01, s);
        samp16h(kb, iy[n] + 1, ix[n] + 1, w11, s);

        float l = 0.f;
        const float* rpn = rp + n * HCC;
        #pragma unroll
        for (int i = 0; i < 16; i++) l += q[i] * (s[i] + rpn[i]);
        logit[n] = l;
    }

    float mx = logit[0];
    #pragma unroll
    for (int n = 1; n < N9; n++) mx = fmaxf(mx, logit[n]);
    float sum = 0.f;
    #pragma unroll
    for (int n = 0; n < N9; n++) { logit[n] = __expf(logit[n] - mx); sum += logit[n]; }
    float inv = 1.f / sum;

    float o16[16];
    #pragma unroll
    for (int i = 0; i < 16; i++) o16[i] = 0.f;

    #pragma unroll
    for (int n = 0; n < N9; n++) {
        float wn = logit[n] * inv;
        float w00 = (1.f - fx[n]) * (1.f - fy[n]) * wn;
        float w10 = fx[n] * (1.f - fy[n]) * wn;
        float w01 = (1.f - fx[n]) * fy[n] * wn;
        float w11 = fx[n] * fy[n] * wn;
        samp16h(vb, iy[n],     ix[n],     w00, o16);
        samp16h(vb, iy[n],     ix[n] + 1, w10, o16);
        samp16h(vb, iy[n] + 1, ix[n],     w01, o16);
        samp16h(vb, iy[n] + 1, ix[n] + 1, w11, o16);
    }

    float* dst = g_attnout + (size_t)p * CRC + nh * HCC;
    #pragma unroll
    for (int i = 0; i < 16; i++) dst[i] = o16[i];
}

// ---------------- launch ----------------
extern "C" void kernel_launch(void* const* d_in, const int* in_sizes, int n_in,
                              void* d_out, int out_size)
{
    const float* x      = (const float*)d_in[0];
    const float* offset = (const float*)d_in[1];
    const float* ln1_g  = (const float*)d_in[2];
    const float* ln1_b  = (const float*)d_in[3];
    const float* w_qkv  = (const float*)d_in[4];
    const float* w_dw   = (const float*)d_in[5];
    const float* ln2_g  = (const float*)d_in[6];
    const float* ln2_b  = (const float*)d_in[7];
    const float* w_off  = (const float*)d_in[8];
    const float* b_off  = (const float*)d_in[9];
    const float* rpb    = (const float*)d_in[10];
    const float* w_proj = (const float*)d_in[11];
    const float* b_proj = (const float*)d_in[12];
    const float* w_cls  = (const float*)d_in[13];
    const float* b_cls  = (const float*)d_in[14];
    float* out = (float*)d_out;

    const int dwSmem  = 3168 * 16;
    const int offSmem = 2112 * 16 + 5184 * 4;
    const int pcSmem  = 24320 * 4;   // 97280 B
    static int configured = 0;
    if (!configured) {
        cudaFuncSetAttribute(k_dw,  cudaFuncAttributeMaxDynamicSharedMemorySize, dwSmem);
        cudaFuncSetAttribute(k_off, cudaFuncAttributeMaxDynamicSharedMemorySize, offSmem);
        cudaFuncSetAttribute(k_projcls, cudaFuncAttributeMaxDynamicSharedMemorySize, pcSmem);
        configured = 1;
    }

    k_ln<<<PP / 32, 256>>>(x, ln1_g, ln1_b);
    k_gemm0<<<dim3(3, PP / 128), 256>>>(w_qkv);
    k_dw<<<16 * 16, 256, dwSmem>>>(w_dw, ln2_g, ln2_b);
    k_off<<<16 * 32, 256, offSmem>>>(w_off, b_off, offset);
    k_attn<<<(PP * 4) / 128, 128>>>(rpb);
    k_projcls<<<PP / 64, 256, pcSmem>>>(w_proj, b_proj, x, w_cls, b_cls, out);
}

// round 15
// speedup vs baseline: 1.1524x; 1.0356x over previous
#include <cuda_runtime.h>
#include <cuda_bf16.h>
#include <cuda_fp16.h>
#include <math.h>

// ---------------- static config ----------------
#define HWP   4096
#define PP    32768
#define DIMC  256
#define CRC   64
#define GCC   32
#define HCC   16
#define N9    9
#define OFFC  18
#define NCLS  80
#define SCALEF 0.25f
#define MULF  5.0f

// ---------------- scratch ----------------
__device__ float  g_qbuf[PP * CRC];
__device__ __half g_kbufh[16 * HWP * GCC];
__device__ __half g_vbufh[16 * HWP * GCC];
__device__ float  g_tbuf[16 * HWP * GCC];
__device__ float  g_offbuf[16 * HWP * OFFC];
__device__ float  g_attnout[PP * CRC];

// ---------------- helpers: bf16 split + mma ----------------
__device__ __forceinline__ void cvt_pair(float x0, float x1,
                                         unsigned& hi, unsigned& lo)
{
    __nv_bfloat16 h0 = __float2bfloat16(x0);
    __nv_bfloat16 h1 = __float2bfloat16(x1);
    float r0 = x0 - __bfloat162float(h0);
    float r1 = x1 - __bfloat162float(h1);
    __nv_bfloat16 l0 = __float2bfloat16(r0);
    __nv_bfloat16 l1 = __float2bfloat16(r1);
    unsigned short u0 = *(unsigned short*)&h0, u1 = *(unsigned short*)&h1;
    unsigned short v0 = *(unsigned short*)&l0, v1 = *(unsigned short*)&l1;
    hi = (unsigned)u0 | ((unsigned)u1 << 16);
    lo = (unsigned)v0 | ((unsigned)v1 << 16);
}

__device__ __forceinline__ void mma_bf16(float* c,
                                         unsigned a0, unsigned a1, unsigned a2, unsigned a3,
                                         unsigned b0, unsigned b1)
{
    asm volatile(
        "mma.sync.aligned.m16n8k16.row.col.f32.bf16.bf16.f32 "
        "{%0,%1,%2,%3}, {%4,%5,%6,%7}, {%8,%9}, {%0,%1,%2,%3};\n"
        : "+f"(c[0]), "+f"(c[1]), "+f"(c[2]), "+f"(c[3])
        : "r"(a0), "r"(a1), "r"(a2), "r"(a3), "r"(b0), "r"(b1));
}

// ---------------- fused LN + qkv GEMM -----------------------------------------
// Block = 64 pixels, 256 threads. BM=64, BN=192 (all qkv outputs), K=256.
// Pass 1: per-pixel LN stats from NCHW x. Pass 2: normalize -> bf16 hi/lo A smem
// (A resident for whole K). MMA loop streams w_qkv in 8 chunks of 32k.
// smem (unsigned units): Ah[8*64*20]=10240, Al=10240, Bh[192*18]=3456, Bl=3456,
// stats 640 floats -> 112,128 B total.
__global__ void __launch_bounds__(256) k_lnqkv(const float* __restrict__ x,
                                               const float* __restrict__ gam,
                                               const float* __restrict__ bet,
                                               const float* __restrict__ Bw)
{
    extern __shared__ unsigned sm[];
    unsigned* Ah = sm;                 // [chunk][64 rows][20]
    unsigned* Al = sm + 10240;
    unsigned* Bh = sm + 20480;         // [192 rows][18]
    unsigned* Bl = sm + 23936;
    float* red   = (float*)(sm + 27392);   // [2][4][64]
    float* meanv = red + 512;               // [64]
    float* rstdv = meanv + 64;               // [64]

    int tid = threadIdx.x;
    int row0 = blockIdx.x * 64;
    int bidx = row0 >> 12;
    int hw0 = row0 & 4095;
    int col = tid & 63;
    int cg  = tid >> 6;                 // 0..3

    const float* xb = x + (size_t)bidx * DIMC * HWP + hw0;

    // ---- pass 1: LN stats ----
    float sum = 0.f, sq = 0.f;
    #pragma unroll 8
    for (int j = 0; j < 32; j++) {
        int c = (cg + j * 4) * 2;
        float v0 = xb[(size_t)c * HWP + col];
        float v1 = xb[(size_t)(c + 1) * HWP + col];
        sum += v0 + v1;
        sq  += v0 * v0 + v1 * v1;
    }
    red[cg * 64 + col] = sum;
    red[256 + cg * 64 + col] = sq;
    __syncthreads();
    if (tid < 64) {
        float s1 = red[tid] + red[64 + tid] + red[128 + tid] + red[192 + tid];
        float s2 = red[256 + tid] + red[320 + tid] + red[384 + tid] + red[448 + tid];
        float m = s1 * (1.f / 256.f);
        float var = s2 * (1.f / 256.f) - m * m;
        meanv[tid] = m;
        rstdv[tid] = rsqrtf(var + 1e-5f);
    }
    __syncthreads();

    // ---- pass 2: normalize + split into resident A smem ----
    float mm = meanv[col], rs = rstdv[col];
    #pragma unroll 8
    for (int j = 0; j < 32; j++) {
        int pi = cg + j * 4;            // pair index 0..127
        int c = pi * 2;
        float v0 = (xb[(size_t)c * HWP + col] - mm) * rs * __ldg(gam + c) + __ldg(bet + c);
        float v1 = (xb[(size_t)(c + 1) * HWP + col] - mm) * rs * __ldg(gam + c + 1) + __ldg(bet + c + 1);
        unsigned hi, lo;
        cvt_pair(v0, v1, hi, lo);
        int chunk = pi >> 4, slot = pi & 15;
        Ah[chunk * 1280 + col * 20 + slot] = hi;
        Al[chunk * 1280 + col * 20 + slot] = lo;
    }
    __syncthreads();

    // ---- MMA mainloop ----
    int lane = tid & 31;
    int warpId = tid >> 5;
    int warpM = warpId & 1;             // 2 x 32 rows
    int warpN = warpId >> 1;            // 4 x 48 cols

    float acc[2][6][4];
    #pragma unroll
    for (int mt = 0; mt < 2; mt++)
        #pragma unroll
        for (int nt = 0; nt < 6; nt++)
            #pragma unroll
            for (int e = 0; e < 4; e++) acc[mt][nt][e] = 0.f;

    for (int ch = 0; ch < 8; ch++) {
        // stage B chunk: 192 rows x 32k = 1536 float4, 6 per thread
        #pragma unroll
        for (int i = 0; i < 6; i++) {
            int u = tid + i * 256;
            int rowb = u >> 3, f = u & 7;
            float4 v = *(const float4*)(Bw + (size_t)rowb * DIMC + ch * 32 + f * 4);
            unsigned h0, l0, h1, l1;
            cvt_pair(v.x, v.y, h0, l0);
            cvt_pair(v.z, v.w, h1, l1);
            Bh[rowb * 18 + f * 2] = h0; Bh[rowb * 18 + f * 2 + 1] = h1;
            Bl[rowb * 18 + f * 2] = l0; Bl[rowb * 18 + f * 2 + 1] = l1;
        }
        __syncthreads();

        const unsigned* Ach = Ah + ch * 1280;
        const unsigned* Acl = Al + ch * 1280;

        #pragma unroll
        for (int kk = 0; kk < 2; kk++) {
            int kb = kk * 8 + (lane & 3);
            unsigned ah[2][4], al[2][4];
            #pragma unroll
            for (int mt = 0; mt < 2; mt++) {
                int ar = warpM * 32 + mt * 16 + (lane >> 2);
                ah[mt][0] = Ach[ar * 20 + kb];       ah[mt][1] = Ach[(ar + 8) * 20 + kb];
                ah[mt][2] = Ach[ar * 20 + kb + 4];   ah[mt][3] = Ach[(ar + 8) * 20 + kb + 4];
                al[mt][0] = Acl[ar * 20 + kb];       al[mt][1] = Acl[(ar + 8) * 20 + kb];
                al[mt][2] = Acl[ar * 20 + kb + 4];   al[mt][3] = Acl[(ar + 8) * 20 + kb + 4];
            }
            #pragma unroll
            for (int nt = 0; nt < 6; nt++) {
                int br = warpN * 48 + nt * 8 + (lane >> 2);
                unsigned bh0 = Bh[br * 18 + kb], bh1 = Bh[br * 18 + kb + 4];
                unsigned bl0 = Bl[br * 18 + kb], bl1 = Bl[br * 18 + kb + 4];
                #pragma unroll
                for (int mt = 0; mt < 2; mt++) {
                    mma_bf16(acc[mt][nt], ah[mt][0], ah[mt][1], ah[mt][2], ah[mt][3], bh0, bh1);
                    mma_bf16(acc[mt][nt], ah[mt][0], ah[mt][1], ah[mt][2], ah[mt][3], bl0, bl1);
                    mma_bf16(acc[mt][nt], al[mt][0], al[mt][1], al[mt][2], al[mt][3], bh0, bh1);
                }
            }
        }
        __syncthreads();
    }

    // ---- epilogue: scatter q / k / v ----
    #pragma unroll
    for (int mt = 0; mt < 2; mt++) {
        #pragma unroll
        for (int nt = 0; nt < 6; nt++) {
            #pragma unroll
            for (int e = 0; e < 4; e++) {
                int p = row0 + warpM * 32 + mt * 16 + (lane >> 2) + ((e >= 2) ? 8 : 0);
                int o = warpN * 48 + nt * 8 + 2 * (lane & 3) + (e & 1);
                float v = acc[mt][nt][e];
                int pb = p >> 12, hw = p & 4095;
                if (o < 64) {
                    g_qbuf[p * 64 + o] = v;
                } else if (o < 128) {
                    int c = o - 64;
                    g_kbufh[((size_t)(pb * 2 + (c >> 5)) * HWP + hw) * GCC + (c & 31)] =
                        __float2half(v);
                } else {
                    int c = o - 128;
                    g_vbufh[((size_t)(pb * 2 + (c >> 5)) * HWP + hw) * GCC + (c & 31)] =
                        __float2half(v);
                }
            }
        }
    }
}

// ---------------- fused proj + residual + cls (R14, unchanged) ----------------
__global__ void __launch_bounds__(256) k_projcls(const float* __restrict__ w_proj,
                                                 const float* __restrict__ b_proj,
                                                 const float* __restrict__ xres,
                                                 const float* __restrict__ w_cls,
                                                 const float* __restrict__ b_cls,
                                                 float* __restrict__ outp)
{
    extern __shared__ unsigned sm[];
    unsigned* yh = sm;
    unsigned* yl = sm + 8320;
    unsigned* Bh = sm + 16640;
    unsigned* Bl = sm + 19200;
    unsigned* Ah = sm + 21760;
    unsigned* Al = sm + 23040;

    int tid = threadIdx.x;
    int lane = tid & 31;
    int warpId = tid >> 5;
    int warpM = warpId & 1;
    int warpN = warpId >> 1;
    int row0 = blockIdx.x * 64;
    int bidx = row0 >> 12;

    for (int nc = 0; nc < 2; nc++) {
        float acc[2][4][4];
        #pragma unroll
        for (int mt = 0; mt < 2; mt++)
            #pragma unroll
            for (int nt = 0; nt < 4; nt++)
                #pragma unroll
                for (int e = 0; e < 4; e++) acc[mt][nt][e] = 0.f;

        for (int k0 = 0; k0 < 64; k0 += 32) {
            #pragma unroll
            for (int i = 0; i < 2; i++) {
                int u = tid + i * 256;
                int row = u >> 3, f = u & 7;
                float4 v = *(const float4*)(g_attnout + (size_t)(row0 + row) * CRC + k0 + f * 4);
                unsigned h0, l0, h1, l1;
                cvt_pair(v.x, v.y, h0, l0);
                cvt_pair(v.z, v.w, h1, l1);
                Ah[row * 20 + f * 2] = h0; Ah[row * 20 + f * 2 + 1] = h1;
                Al[row * 20 + f * 2] = l0; Al[row * 20 + f * 2 + 1] = l1;
            }
            #pragma unroll
            for (int i = 0; i < 4; i++) {
                int u = tid + i * 256;
                int row = u >> 3, f = u & 7;
                float4 v = *(const float4*)(w_proj + (size_t)(nc * 128 + row) * CRC + k0 + f * 4);
                unsigned h0, l0, h1, l1;
                cvt_pair(v.x, v.y, h0, l0);
                cvt_pair(v.z, v.w, h1, l1);
                Bh[row * 20 + f * 2] = h0; Bh[row * 20 + f * 2 + 1] = h1;
                Bl[row * 20 + f * 2] = l0; Bl[row * 20 + f * 2 + 1] = l1;
            }
            __syncthreads();

            #pragma unroll
            for (int kk = 0; kk < 2; kk++) {
                int kb = kk * 8 + (lane & 3);
                unsigned ah[2][4], al[2][4];
                #pragma unroll
                for (int mt = 0; mt < 2; mt++) {
                    int ar = warpM * 32 + mt * 16 + (lane >> 2);
                    ah[mt][0] = Ah[ar * 20 + kb];       ah[mt][1] = Ah[(ar + 8) * 20 + kb];
                    ah[mt][2] = Ah[ar * 20 + kb + 4];   ah[mt][3] = Ah[(ar + 8) * 20 + kb + 4];
                    al[mt][0] = Al[ar * 20 + kb];       al[mt][1] = Al[(ar + 8) * 20 + kb];
                    al[mt][2] = Al[ar * 20 + kb + 4];   al[mt][3] = Al[(ar + 8) * 20 + kb + 4];
                }
                #pragma unroll
                for (int nt = 0; nt < 4; nt++) {
                    int br = warpN * 32 + nt * 8 + (lane >> 2);
                    unsigned bh0 = Bh[br * 20 + kb], bh1 = Bh[br * 20 + kb + 4];
                    unsigned bl0 = Bl[br * 20 + kb], bl1 = Bl[br * 20 + kb + 4];
                    #pragma unroll
                    for (int mt = 0; mt < 2; mt++) {
                        mma_bf16(acc[mt][nt], ah[mt][0], ah[mt][1], ah[mt][2], ah[mt][3], bh0, bh1);
                        mma_bf16(acc[mt][nt], ah[mt][0], ah[mt][1], ah[mt][2], ah[mt][3], bl0, bl1);
                        mma_bf16(acc[mt][nt], al[mt][0], al[mt][1], al[mt][2], al[mt][3], bh0, bh1);
                    }
                }
            }
            __syncthreads();
        }

        #pragma unroll
        for (int mt = 0; mt < 2; mt++) {
            #pragma unroll
            for (int nt = 0; nt < 4; nt++) {
                #pragma unroll
                for (int ep = 0; ep < 2; ep++) {
                    int r = warpM * 32 + mt * 16 + (lane >> 2) + ep * 8;
                    int p = row0 + r;
                    int hw = p & 4095;
                    int o0 = nc * 128 + warpN * 32 + nt * 8 + 2 * (lane & 3);
                    float v0 = acc[mt][nt][ep * 2] + b_proj[o0]
                             + xres[(size_t)bidx * DIMC * HWP + (size_t)o0 * HWP + hw];
                    float v1 = acc[mt][nt][ep * 2 + 1] + b_proj[o0 + 1]
                             + xres[(size_t)bidx * DIMC * HWP + (size_t)(o0 + 1) * HWP + hw];
                    unsigned hi, lo;
                    cvt_pair(v0, v1, hi, lo);
                    yh[r * 130 + (o0 >> 1)] = hi;
                    yl[r * 130 + (o0 >> 1)] = lo;
                }
            }
        }
        __syncthreads();
    }

    float acc2[2][3][4];
    #pragma unroll
    for (int mt = 0; mt < 2; mt++)
        #pragma unroll
        for (int nt = 0; nt < 3; nt++)
            #pragma unroll
            for (int e = 0; e < 4; e++) acc2[mt][nt][e] = 0.f;

    for (int kc = 0; kc < 8; kc++) {
        #pragma unroll
        for (int i = 0; i < 3; i++) {
            int u = tid + i * 256;
            int row = u >> 3, f = u & 7;
            float4 v = make_float4(0.f, 0.f, 0.f, 0.f);
            if (row < NCLS)
                v = *(const float4*)(w_cls + (size_t)row * DIMC + kc * 32 + f * 4);
            unsigned h0, l0, h1, l1;
            cvt_pair(v.x, v.y, h0, l0);
            cvt_pair(v.z, v.w, h1, l1);
            Bh[row * 20 + f * 2] = h0; Bh[row * 20 + f * 2 + 1] = h1;
            Bl[row * 20 + f * 2] = l0; Bl[row * 20 + f * 2 + 1] = l1;
        }
        __syncthreads();

        int kbase = kc * 16;
        #pragma unroll
        for (int kk = 0; kk < 2; kk++) {
            int kb = kk * 8 + (lane & 3);
            unsigned ah[2][4], al[2][4];
            #pragma unroll
            for (int mt = 0; mt < 2; mt++) {
                int ar = warpM * 32 + mt * 16 + (lane >> 2);
                ah[mt][0] = yh[ar * 130 + kbase + kb];
                ah[mt][1] = yh[(ar + 8) * 130 + kbase + kb];
                ah[mt][2] = yh[ar * 130 + kbase + kb + 4];
                ah[mt][3] = yh[(ar + 8) * 130 + kbase + kb + 4];
                al[mt][0] = yl[ar * 130 + kbase + kb];
                al[mt][1] = yl[(ar + 8) * 130 + kbase + kb];
                al[mt][2] = yl[ar * 130 + kbase + kb + 4];
                al[mt][3] = yl[(ar + 8) * 130 + kbase + kb + 4];
            }
            #pragma unroll
            for (int nt = 0; nt < 3; nt++) {
                int br = warpN * 24 + nt * 8 + (lane >> 2);
                unsigned bh0 = Bh[br * 20 + kb], bh1 = Bh[br * 20 + kb + 4];
                unsigned bl0 = Bl[br * 20 + kb], bl1 = Bl[br * 20 + kb + 4];
                #pragma unroll
                for (int mt = 0; mt < 2; mt++) {
                    mma_bf16(acc2[mt][nt], ah[mt][0], ah[mt][1], ah[mt][2], ah[mt][3], bh0, bh1);
                    mma_bf16(acc2[mt][nt], ah[mt][0], ah[mt][1], ah[mt][2], ah[mt][3], bl0, bl1);
                    mma_bf16(acc2[mt][nt], al[mt][0], al[mt][1], al[mt][2], al[mt][3], bh0, bh1);
                }
            }
        }
        __syncthreads();
    }

    #pragma unroll
    for (int mt = 0; mt < 2; mt++) {
        #pragma unroll
        for (int nt = 0; nt < 3; nt++) {
            #pragma unroll
            for (int e = 0; e < 4; e++) {
                int p = row0 + warpM * 32 + mt * 16 + (lane >> 2) + ((e >= 2) ? 8 : 0);
                int o = warpN * 24 + nt * 8 + 2 * (lane & 3) + (e & 1);
                int hw = p & 4095;
                if (o < NCLS)
                    outp[(size_t)bidx * NCLS * HWP + (size_t)o * HWP + hw] =
                        acc2[mt][nt][e] + b_cls[o];
            }
        }
    }
}

// ---------------- kernel 3: smem-tiled depthwise 3x3 + LN(32) + GELU ----------
__global__ void __launch_bounds__(256, 2) k_dw(const float* __restrict__ wdw,
                                               const float* __restrict__ g2,
                                               const float* __restrict__ b2)
{
    extern __shared__ float4 st4[];
    __shared__ float sw[GCC * 9];
    __shared__ float sg[GCC], sb[GCC];

    int bg = blockIdx.x >> 4;
    int h0 = (blockIdx.x & 15) * 4;
    int b = bg >> 1, g = bg & 1;
    int tid = threadIdx.x;

    for (int i = tid; i < GCC * 9; i += 256) sw[i] = wdw[i];
    if (tid < GCC) { sg[tid] = g2[tid]; sb[tid] = b2[tid]; }
    for (int i = tid; i < 3168; i += 256) st4[i] = make_float4(0.f, 0.f, 0.f, 0.f);
    __syncthreads();

    for (int i = tid; i < 3072; i += 256) {
        int c4 = i & 7, col = (i >> 3) & 63, r = i >> 9;
        int gr = h0 - 1 + r;
        if ((unsigned)gr < 64u)
            st4[(c4 * 6 + r) * 66 + col + 1] =
                *(const float4*)(g_qbuf + ((size_t)(b * HWP + gr * 64 + col)) * CRC + g * GCC + c4 * 4);
    }
    __syncthreads();

    int col = tid & 63;
    int row = tid >> 6;
    int h = h0 + row;

    float acc[GCC];
    #pragma unroll
    for (int c = 0; c < GCC; c++) acc[c] = 0.f;

    #pragma unroll
    for (int ky = 0; ky < 3; ky++) {
        #pragma unroll
        for (int kx = 0; kx < 3; kx++) {
            int kidx = ky * 3 + kx;
            #pragma unroll
            for (int c4 = 0; c4 < 8; c4++) {
                float4 v = st4[(c4 * 6 + row + ky) * 66 + col + kx];
                acc[c4 * 4 + 0] += v.x * sw[(c4 * 4 + 0) * 9 + kidx];
                acc[c4 * 4 + 1] += v.y * sw[(c4 * 4 + 1) * 9 + kidx];
                acc[c4 * 4 + 2] += v.z * sw[(c4 * 4 + 2) * 9 + kidx];
                acc[c4 * 4 + 3] += v.w * sw[(c4 * 4 + 3) * 9 + kidx];
            }
        }
    }

    float m = 0.f;
    #pragma unroll
    for (int c = 0; c < GCC; c++) m += acc[c];
    m *= (1.f / GCC);
    float v = 0.f;
    #pragma unroll
    for (int c = 0; c < GCC; c++) { float d = acc[c] - m; v += d * d; }
    float rs = rsqrtf(v * (1.f / GCC) + 1e-5f);

    float* dst = g_tbuf + ((size_t)bg * HWP + h * 64 + col) * GCC;
    #pragma unroll
    for (int c = 0; c < GCC; c++) {
        float t = (acc[c] - m) * rs * sg[c] + sb[c];
        dst[c] = 0.5f * t * (1.f + erff(t * 0.70710678118654752f));
    }
}

// ---------------- kernel 4: smem-tiled 3x3 conv (32->18), 2 rows/block --------
__global__ void __launch_bounds__(256) k_off(const float* __restrict__ woff,
                                             const float* __restrict__ boff,
                                             const float* __restrict__ offset)
{
    extern __shared__ float4 dyn4[];
    float4* st4 = dyn4;
    float*  sw  = (float*)(dyn4 + 2112);
    float4* sw4 = (float4*)sw;

    int bg = blockIdx.x >> 5;
    int h0 = (blockIdx.x & 31) * 2;
    int tid = threadIdx.x;

    for (int i = tid; i < OFFC * GCC * 9; i += 256) {
        int o = i / (GCC * 9); int rem = i - o * (GCC * 9);
        int c = rem / 9; int kidx = rem - c * 9;
        sw[(kidx * OFFC + o) * GCC + c] = woff[i];
    }
    for (int i = tid; i < 2112; i += 256) st4[i] = make_float4(0.f, 0.f, 0.f, 0.f);
    __syncthreads();

    for (int i = tid; i < 2048; i += 256) {
        int c4 = i & 7, col = (i >> 3) & 63, r = i >> 9;
        int gr = h0 - 1 + r;
        if ((unsigned)gr < 64u)
            st4[(c4 * 4 + r) * 66 + col + 1] =
                *(const float4*)(g_tbuf + ((size_t)(bg * HWP + gr * 64 + col)) * GCC + c4 * 4);
    }
    __syncthreads();

    int col = tid & 63;
    int og  = (tid >> 6) & 1;
    int row = tid >> 7;
    int h = h0 + row;
    int b = bg >> 1;

    float acc[9];
    #pragma unroll
    for (int o = 0; o < 9; o++) acc[o] = boff[og * 9 + o];

    #pragma unroll
    for (int c4 = 0; c4 < 8; c4++) {
        #pragma unroll
        for (int ky = 0; ky < 3; ky++) {
            const float4* trow = &st4[(c4 * 4 + row + ky) * 66];
            float4 t[3];
            t[0] = trow[col]; t[1] = trow[col + 1]; t[2] = trow[col + 2];
            #pragma unroll
            for (int kx = 0; kx < 3; kx++) {
                int kidx = ky * 3 + kx;
                #pragma unroll
                for (int o = 0; o < 9; o++) {
                    float4 w = sw4[(kidx * OFFC + og * 9 + o) * 8 + c4];
                    acc[o] += t[kx].x * w.x + t[kx].y * w.y +
                              t[kx].z * w.z + t[kx].w * w.w;
                }
            }
        }
    }

    int hw = h * 64 + col;
    const float* ofs = offset + (size_t)b * OFFC * HWP + hw;
    float* dst = g_offbuf + ((size_t)bg * HWP + hw) * OFFC + og * 9;
    #pragma unroll
    for (int o = 0; o < 9; o++)
        dst[o] = tanhf(acc[o]) * MULF + ofs[(og * 9 + o) * HWP];
}

// ---------------- kernel 5: deformable gather + softmax attention (fp16 k/v) ---
__device__ __forceinline__ void samp16h(const __half* __restrict__ bufh,
                                        int y, int x, float w, float s[16])
{
    if ((unsigned)x < 64u && (unsigned)y < 64u) {
        const uint4* q = (const uint4*)(bufh + (y * 64 + x) * GCC);
        uint4 u0 = q[0], u1 = q[1];
        const __half2* h0 = (const __half2*)&u0;
        const __half2* h1 = (const __half2*)&u1;
        #pragma unroll
        for (int i = 0; i < 4; i++) {
            float2 f = __half22float2(h0[i]);
            s[2 * i]     += w * f.x;
            s[2 * i + 1] += w * f.y;
        }
        #pragma unroll
        for (int i = 0; i < 4; i++) {
            float2 f = __half22float2(h1[i]);
            s[8 + 2 * i]     += w * f.x;
            s[8 + 2 * i + 1] += w * f.y;
        }
    }
}

__global__ void k_attn(const float* __restrict__ rpb)
{
    int idx = blockIdx.x * blockDim.x + threadIdx.x;
    int nh = idx & 3;
    int p  = idx >> 2;
    int b = p >> 12, hw = p & 4095;
    int g = nh >> 1, hb = (nh & 1) * 16;
    int bg = b * 2 + g;

    float q[16];
    const float* qp = g_qbuf + (size_t)p * CRC + nh * HCC;
    #pragma unroll
    for (int i = 0; i < 16; i++) q[i] = qp[i] * SCALEF;

    const float* off = g_offbuf + (size_t)(bg * HWP + hw) * OFFC;
    const __half* kb = g_kbufh + (size_t)bg * HWP * GCC + hb;
    const __half* vb = g_vbufh + (size_t)bg * HWP * GCC + hb;
    const float* rp = rpb + nh * (N9 * HCC);

    int ix[N9], iy[N9];
    float fx[N9], fy[N9], logit[N9];

    #pragma unroll
    for (int n = 0; n < N9; n++) {
        float row = off[2 * n], col = off[2 * n + 1];
        float xf = floorf(col), yf = floorf(row);
        ix[n] = (int)xf; iy[n] = (int)yf;
        fx[n] = col - xf; fy[n] = row - yf;

        float w00 = (1.f - fx[n]) * (1.f - fy[n]);
        float w10 = fx[n] * (1.f - fy[n]);
        float w01 = (1.f - fx[n]) * fy[n];
        float w11 = fx[n] * fy[n];

        float s[16];
        #pragma unroll
        for (int i = 0; i < 16; i++) s[i] = 0.f;
        samp16h(kb, iy[n],     ix[n],     w00, s);
        samp16h(kb, iy[n],     ix[n] + 1, w10, s);
        samp16h(kb, iy[n] + 1, ix[n],     w01, s);
        samp16h(kb, iy[n] + 1, ix[n] + 1, w11, s);

        float l = 0.f;
        const float* rpn = rp + n * HCC;
        #pragma unroll
        for (int i = 0; i < 16; i++) l += q[i] * (s[i] + rpn[i]);
        logit[n] = l;
    }

    float mx = logit[0];
    #pragma unroll
    for (int n = 1; n < N9; n++) mx = fmaxf(mx, logit[n]);
    float sum = 0.f;
    #pragma unroll
    for (int n = 0; n < N9; n++) { logit[n] = __expf(logit[n] - mx); sum += logit[n]; }
    float inv = 1.f / sum;

    float o16[16];
    #pragma unroll
    for (int i = 0; i < 16; i++) o16[i] = 0.f;

    #pragma unroll
    for (int n = 0; n < N9; n++) {
        float wn = logit[n] * inv;
        float w00 = (1.f - fx[n]) * (1.f - fy[n]) * wn;
        float w10 = fx[n] * (1.f - fy[n]) * wn;
        float w01 = (1.f - fx[n]) * fy[n] * wn;
        float w11 = fx[n] * fy[n] * wn;
        samp16h(vb, iy[n],     ix[n],     w00, o16);
        samp16h(vb, iy[n],     ix[n] + 1, w10, o16);
        samp16h(vb, iy[n] + 1, ix[n],     w01, o16);
        samp16h(vb, iy[n] + 1, ix[n] + 1, w11, o16);
    }

    float* dst = g_attnout + (size_t)p * CRC + nh * HCC;
    #pragma unroll
    for (int i = 0; i < 16; i++) dst[i] = o16[i];
}

// ---------------- launch ----------------
extern "C" void kernel_launch(void* const* d_in, const int* in_sizes, int n_in,
                              void* d_out, int out_size)
{
    const float* x      = (const float*)d_in[0];
    const float* offset = (const float*)d_in[1];
    const float* ln1_g  = (const float*)d_in[2];
    const float* ln1_b  = (const float*)d_in[3];
    const float* w_qkv  = (const float*)d_in[4];
    const float* w_dw   = (const float*)d_in[5];
    const float* ln2_g  = (const float*)d_in[6];
    const float* ln2_b  = (const float*)d_in[7];
    const float* w_off  = (const float*)d_in[8];
    const float* b_off  = (const float*)d_in[9];
    const float* rpb    = (const float*)d_in[10];
    const float* w_proj = (const float*)d_in[11];
    const float* b_proj = (const float*)d_in[12];
    const float* w_cls  = (const float*)d_in[13];
    const float* b_cls  = (const float*)d_in[14];
    float* out = (float*)d_out;

    const int dwSmem  = 3168 * 16;
    const int offSmem = 2112 * 16 + 5184 * 4;
    const int pcSmem  = 24320 * 4;    // 97280 B
    const int lqSmem  = 28032 * 4;    // 112128 B
    static int configured = 0;
    if (!configured) {
        cudaFuncSetAttribute(k_dw,  cudaFuncAttributeMaxDynamicSharedMemorySize, dwSmem);
        cudaFuncSetAttribute(k_off, cudaFuncAttributeMaxDynamicSharedMemorySize, offSmem);
        cudaFuncSetAttribute(k_projcls, cudaFuncAttributeMaxDynamicSharedMemorySize, pcSmem);
        cudaFuncSetAttribute(k_lnqkv, cudaFuncAttributeMaxDynamicSharedMemorySize, lqSmem);
        configured = 1;
    }

    k_lnqkv<<<PP / 64, 256, lqSmem>>>(x, ln1_g, ln1_b, w_qkv);
    k_dw<<<16 * 16, 256, dwSmem>>>(w_dw, ln2_g, ln2_b);
    k_off<<<16 * 32, 256, offSmem>>>(w_off, b_off, offset);
    k_attn<<<(PP * 4) / 128, 128>>>(rpb);
    k_projcls<<<PP / 64, 256, pcSmem>>>(w_proj, b_proj, x, w_cls, b_cls, out);
}

// round 16
// speedup vs baseline: 1.2248x; 1.0629x over previous
#include <cuda_runtime.h>
#include <cuda_bf16.h>
#include <cuda_fp16.h>
#include <math.h>

// ---------------- static config ----------------
#define HWP   4096
#define PP    32768
#define DIMC  256
#define CRC   64
#define GCC   32
#define HCC   16
#define N9    9
#define OFFC  18
#define NCLS  80
#define SCALEF 0.25f
#define MULF  5.0f

// ---------------- scratch ----------------
__device__ float  g_qbuf[PP * CRC];
__device__ __half g_kbufh[16 * HWP * GCC];
__device__ __half g_vbufh[16 * HWP * GCC];
__device__ float  g_tbuf[16 * HWP * GCC];
__device__ float  g_offbuf[16 * HWP * OFFC];
__device__ float  g_attnout[PP * CRC];

// ---------------- helpers: bf16 split + mma ----------------
__device__ __forceinline__ void cvt_pair(float x0, float x1,
                                         unsigned& hi, unsigned& lo)
{
    __nv_bfloat16 h0 = __float2bfloat16(x0);
    __nv_bfloat16 h1 = __float2bfloat16(x1);
    float r0 = x0 - __bfloat162float(h0);
    float r1 = x1 - __bfloat162float(h1);
    __nv_bfloat16 l0 = __float2bfloat16(r0);
    __nv_bfloat16 l1 = __float2bfloat16(r1);
    unsigned short u0 = *(unsigned short*)&h0, u1 = *(unsigned short*)&h1;
    unsigned short v0 = *(unsigned short*)&l0, v1 = *(unsigned short*)&l1;
    hi = (unsigned)u0 | ((unsigned)u1 << 16);
    lo = (unsigned)v0 | ((unsigned)v1 << 16);
}

__device__ __forceinline__ void mma_bf16(float* c,
                                         unsigned a0, unsigned a1, unsigned a2, unsigned a3,
                                         unsigned b0, unsigned b1)
{
    asm volatile(
        "mma.sync.aligned.m16n8k16.row.col.f32.bf16.bf16.f32 "
        "{%0,%1,%2,%3}, {%4,%5,%6,%7}, {%8,%9}, {%0,%1,%2,%3};\n"
        : "+f"(c[0]), "+f"(c[1]), "+f"(c[2]), "+f"(c[3])
        : "r"(a0), "r"(a1), "r"(a2), "r"(a3), "r"(b0), "r"(b1));
}

// ---------------- fused LN + qkv GEMM (R15, unchanged) -------------------------
__global__ void __launch_bounds__(256) k_lnqkv(const float* __restrict__ x,
                                               const float* __restrict__ gam,
                                               const float* __restrict__ bet,
                                               const float* __restrict__ Bw)
{
    extern __shared__ unsigned sm[];
    unsigned* Ah = sm;
    unsigned* Al = sm + 10240;
    unsigned* Bh = sm + 20480;
    unsigned* Bl = sm + 23936;
    float* red   = (float*)(sm + 27392);
    float* meanv = red + 512;
    float* rstdv = meanv + 64;

    int tid = threadIdx.x;
    int row0 = blockIdx.x * 64;
    int bidx = row0 >> 12;
    int hw0 = row0 & 4095;
    int col = tid & 63;
    int cg  = tid >> 6;

    const float* xb = x + (size_t)bidx * DIMC * HWP + hw0;

    float sum = 0.f, sq = 0.f;
    #pragma unroll 8
    for (int j = 0; j < 32; j++) {
        int c = (cg + j * 4) * 2;
        float v0 = xb[(size_t)c * HWP + col];
        float v1 = xb[(size_t)(c + 1) * HWP + col];
        sum += v0 + v1;
        sq  += v0 * v0 + v1 * v1;
    }
    red[cg * 64 + col] = sum;
    red[256 + cg * 64 + col] = sq;
    __syncthreads();
    if (tid < 64) {
        float s1 = red[tid] + red[64 + tid] + red[128 + tid] + red[192 + tid];
        float s2 = red[256 + tid] + red[320 + tid] + red[384 + tid] + red[448 + tid];
        float m = s1 * (1.f / 256.f);
        float var = s2 * (1.f / 256.f) - m * m;
        meanv[tid] = m;
        rstdv[tid] = rsqrtf(var + 1e-5f);
    }
    __syncthreads();

    float mm = meanv[col], rs = rstdv[col];
    #pragma unroll 8
    for (int j = 0; j < 32; j++) {
        int pi = cg + j * 4;
        int c = pi * 2;
        float v0 = (xb[(size_t)c * HWP + col] - mm) * rs * __ldg(gam + c) + __ldg(bet + c);
        float v1 = (xb[(size_t)(c + 1) * HWP + col] - mm) * rs * __ldg(gam + c + 1) + __ldg(bet + c + 1);
        unsigned hi, lo;
        cvt_pair(v0, v1, hi, lo);
        int chunk = pi >> 4, slot = pi & 15;
        Ah[chunk * 1280 + col * 20 + slot] = hi;
        Al[chunk * 1280 + col * 20 + slot] = lo;
    }
    __syncthreads();

    int lane = tid & 31;
    int warpId = tid >> 5;
    int warpM = warpId & 1;
    int warpN = warpId >> 1;

    float acc[2][6][4];
    #pragma unroll
    for (int mt = 0; mt < 2; mt++)
        #pragma unroll
        for (int nt = 0; nt < 6; nt++)
            #pragma unroll
            for (int e = 0; e < 4; e++) acc[mt][nt][e] = 0.f;

    for (int ch = 0; ch < 8; ch++) {
        #pragma unroll
        for (int i = 0; i < 6; i++) {
            int u = tid + i * 256;
            int rowb = u >> 3, f = u & 7;
            float4 v = *(const float4*)(Bw + (size_t)rowb * DIMC + ch * 32 + f * 4);
            unsigned h0, l0, h1, l1;
            cvt_pair(v.x, v.y, h0, l0);
            cvt_pair(v.z, v.w, h1, l1);
            Bh[rowb * 18 + f * 2] = h0; Bh[rowb * 18 + f * 2 + 1] = h1;
            Bl[rowb * 18 + f * 2] = l0; Bl[rowb * 18 + f * 2 + 1] = l1;
        }
        __syncthreads();

        const unsigned* Ach = Ah + ch * 1280;
        const unsigned* Acl = Al + ch * 1280;

        #pragma unroll
        for (int kk = 0; kk < 2; kk++) {
            int kb = kk * 8 + (lane & 3);
            unsigned ah[2][4], al[2][4];
            #pragma unroll
            for (int mt = 0; mt < 2; mt++) {
                int ar = warpM * 32 + mt * 16 + (lane >> 2);
                ah[mt][0] = Ach[ar * 20 + kb];       ah[mt][1] = Ach[(ar + 8) * 20 + kb];
                ah[mt][2] = Ach[ar * 20 + kb + 4];   ah[mt][3] = Ach[(ar + 8) * 20 + kb + 4];
                al[mt][0] = Acl[ar * 20 + kb];       al[mt][1] = Acl[(ar + 8) * 20 + kb];
                al[mt][2] = Acl[ar * 20 + kb + 4];   al[mt][3] = Acl[(ar + 8) * 20 + kb + 4];
            }
            #pragma unroll
            for (int nt = 0; nt < 6; nt++) {
                int br = warpN * 48 + nt * 8 + (lane >> 2);
                unsigned bh0 = Bh[br * 18 + kb], bh1 = Bh[br * 18 + kb + 4];
                unsigned bl0 = Bl[br * 18 + kb], bl1 = Bl[br * 18 + kb + 4];
                #pragma unroll
                for (int mt = 0; mt < 2; mt++) {
                    mma_bf16(acc[mt][nt], ah[mt][0], ah[mt][1], ah[mt][2], ah[mt][3], bh0, bh1);
                    mma_bf16(acc[mt][nt], ah[mt][0], ah[mt][1], ah[mt][2], ah[mt][3], bl0, bl1);
                    mma_bf16(acc[mt][nt], al[mt][0], al[mt][1], al[mt][2], al[mt][3], bh0, bh1);
                }
            }
        }
        __syncthreads();
    }

    #pragma unroll
    for (int mt = 0; mt < 2; mt++) {
        #pragma unroll
        for (int nt = 0; nt < 6; nt++) {
            #pragma unroll
            for (int e = 0; e < 4; e++) {
                int p = row0 + warpM * 32 + mt * 16 + (lane >> 2) + ((e >= 2) ? 8 : 0);
                int o = warpN * 48 + nt * 8 + 2 * (lane & 3) + (e & 1);
                float v = acc[mt][nt][e];
                int pb = p >> 12, hw = p & 4095;
                if (o < 64) {
                    g_qbuf[p * 64 + o] = v;
                } else if (o < 128) {
                    int c = o - 64;
                    g_kbufh[((size_t)(pb * 2 + (c >> 5)) * HWP + hw) * GCC + (c & 31)] =
                        __float2half(v);
                } else {
                    int c = o - 128;
                    g_vbufh[((size_t)(pb * 2 + (c >> 5)) * HWP + hw) * GCC + (c & 31)] =
                        __float2half(v);
                }
            }
        }
    }
}

// ---------------- fused proj + residual + cls (R14, unchanged) ----------------
__global__ void __launch_bounds__(256) k_projcls(const float* __restrict__ w_proj,
                                                 const float* __restrict__ b_proj,
                                                 const float* __restrict__ xres,
                                                 const float* __restrict__ w_cls,
                                                 const float* __restrict__ b_cls,
                                                 float* __restrict__ outp)
{
    extern __shared__ unsigned sm[];
    unsigned* yh = sm;
    unsigned* yl = sm + 8320;
    unsigned* Bh = sm + 16640;
    unsigned* Bl = sm + 19200;
    unsigned* Ah = sm + 21760;
    unsigned* Al = sm + 23040;

    int tid = threadIdx.x;
    int lane = tid & 31;
    int warpId = tid >> 5;
    int warpM = warpId & 1;
    int warpN = warpId >> 1;
    int row0 = blockIdx.x * 64;
    int bidx = row0 >> 12;

    for (int nc = 0; nc < 2; nc++) {
        float acc[2][4][4];
        #pragma unroll
        for (int mt = 0; mt < 2; mt++)
            #pragma unroll
            for (int nt = 0; nt < 4; nt++)
                #pragma unroll
                for (int e = 0; e < 4; e++) acc[mt][nt][e] = 0.f;

        for (int k0 = 0; k0 < 64; k0 += 32) {
            #pragma unroll
            for (int i = 0; i < 2; i++) {
                int u = tid + i * 256;
                int row = u >> 3, f = u & 7;
                float4 v = *(const float4*)(g_attnout + (size_t)(row0 + row) * CRC + k0 + f * 4);
                unsigned h0, l0, h1, l1;
                cvt_pair(v.x, v.y, h0, l0);
                cvt_pair(v.z, v.w, h1, l1);
                Ah[row * 20 + f * 2] = h0; Ah[row * 20 + f * 2 + 1] = h1;
                Al[row * 20 + f * 2] = l0; Al[row * 20 + f * 2 + 1] = l1;
            }
            #pragma unroll
            for (int i = 0; i < 4; i++) {
                int u = tid + i * 256;
                int row = u >> 3, f = u & 7;
                float4 v = *(const float4*)(w_proj + (size_t)(nc * 128 + row) * CRC + k0 + f * 4);
                unsigned h0, l0, h1, l1;
                cvt_pair(v.x, v.y, h0, l0);
                cvt_pair(v.z, v.w, h1, l1);
                Bh[row * 20 + f * 2] = h0; Bh[row * 20 + f * 2 + 1] = h1;
                Bl[row * 20 + f * 2] = l0; Bl[row * 20 + f * 2 + 1] = l1;
            }
            __syncthreads();

            #pragma unroll
            for (int kk = 0; kk < 2; kk++) {
                int kb = kk * 8 + (lane & 3);
                unsigned ah[2][4], al[2][4];
                #pragma unroll
                for (int mt = 0; mt < 2; mt++) {
                    int ar = warpM * 32 + mt * 16 + (lane >> 2);
                    ah[mt][0] = Ah[ar * 20 + kb];       ah[mt][1] = Ah[(ar + 8) * 20 + kb];
                    ah[mt][2] = Ah[ar * 20 + kb + 4];   ah[mt][3] = Ah[(ar + 8) * 20 + kb + 4];
                    al[mt][0] = Al[ar * 20 + kb];       al[mt][1] = Al[(ar + 8) * 20 + kb];
                    al[mt][2] = Al[ar * 20 + kb + 4];   al[mt][3] = Al[(ar + 8) * 20 + kb + 4];
                }
                #pragma unroll
                for (int nt = 0; nt < 4; nt++) {
                    int br = warpN * 32 + nt * 8 + (lane >> 2);
                    unsigned bh0 = Bh[br * 20 + kb], bh1 = Bh[br * 20 + kb + 4];
                    unsigned bl0 = Bl[br * 20 + kb], bl1 = Bl[br * 20 + kb + 4];
                    #pragma unroll
                    for (int mt = 0; mt < 2; mt++) {
                        mma_bf16(acc[mt][nt], ah[mt][0], ah[mt][1], ah[mt][2], ah[mt][3], bh0, bh1);
                        mma_bf16(acc[mt][nt], ah[mt][0], ah[mt][1], ah[mt][2], ah[mt][3], bl0, bl1);
                        mma_bf16(acc[mt][nt], al[mt][0], al[mt][1], al[mt][2], al[mt][3], bh0, bh1);
                    }
                }
            }
            __syncthreads();
        }

        #pragma unroll
        for (int mt = 0; mt < 2; mt++) {
            #pragma unroll
            for (int nt = 0; nt < 4; nt++) {
                #pragma unroll
                for (int ep = 0; ep < 2; ep++) {
                    int r = warpM * 32 + mt * 16 + (lane >> 2) + ep * 8;
                    int p = row0 + r;
                    int hw = p & 4095;
                    int o0 = nc * 128 + warpN * 32 + nt * 8 + 2 * (lane & 3);
                    float v0 = acc[mt][nt][ep * 2] + b_proj[o0]
                             + xres[(size_t)bidx * DIMC * HWP + (size_t)o0 * HWP + hw];
                    float v1 = acc[mt][nt][ep * 2 + 1] + b_proj[o0 + 1]
                             + xres[(size_t)bidx * DIMC * HWP + (size_t)(o0 + 1) * HWP + hw];
                    unsigned hi, lo;
                    cvt_pair(v0, v1, hi, lo);
                    yh[r * 130 + (o0 >> 1)] = hi;
                    yl[r * 130 + (o0 >> 1)] = lo;
                }
            }
        }
        __syncthreads();
    }

    float acc2[2][3][4];
    #pragma unroll
    for (int mt = 0; mt < 2; mt++)
        #pragma unroll
        for (int nt = 0; nt < 3; nt++)
            #pragma unroll
            for (int e = 0; e < 4; e++) acc2[mt][nt][e] = 0.f;

    for (int kc = 0; kc < 8; kc++) {
        #pragma unroll
        for (int i = 0; i < 3; i++) {
            int u = tid + i * 256;
            int row = u >> 3, f = u & 7;
            float4 v = make_float4(0.f, 0.f, 0.f, 0.f);
            if (row < NCLS)
                v = *(const float4*)(w_cls + (size_t)row * DIMC + kc * 32 + f * 4);
            unsigned h0, l0, h1, l1;
            cvt_pair(v.x, v.y, h0, l0);
            cvt_pair(v.z, v.w, h1, l1);
            Bh[row * 20 + f * 2] = h0; Bh[row * 20 + f * 2 + 1] = h1;
            Bl[row * 20 + f * 2] = l0; Bl[row * 20 + f * 2 + 1] = l1;
        }
        __syncthreads();

        int kbase = kc * 16;
        #pragma unroll
        for (int kk = 0; kk < 2; kk++) {
            int kb = kk * 8 + (lane & 3);
            unsigned ah[2][4], al[2][4];
            #pragma unroll
            for (int mt = 0; mt < 2; mt++) {
                int ar = warpM * 32 + mt * 16 + (lane >> 2);
                ah[mt][0] = yh[ar * 130 + kbase + kb];
                ah[mt][1] = yh[(ar + 8) * 130 + kbase + kb];
                ah[mt][2] = yh[ar * 130 + kbase + kb + 4];
                ah[mt][3] = yh[(ar + 8) * 130 + kbase + kb + 4];
                al[mt][0] = yl[ar * 130 + kbase + kb];
                al[mt][1] = yl[(ar + 8) * 130 + kbase + kb];
                al[mt][2] = yl[ar * 130 + kbase + kb + 4];
                al[mt][3] = yl[(ar + 8) * 130 + kbase + kb + 4];
            }
            #pragma unroll
            for (int nt = 0; nt < 3; nt++) {
                int br = warpN * 24 + nt * 8 + (lane >> 2);
                unsigned bh0 = Bh[br * 20 + kb], bh1 = Bh[br * 20 + kb + 4];
                unsigned bl0 = Bl[br * 20 + kb], bl1 = Bl[br * 20 + kb + 4];
                #pragma unroll
                for (int mt = 0; mt < 2; mt++) {
                    mma_bf16(acc2[mt][nt], ah[mt][0], ah[mt][1], ah[mt][2], ah[mt][3], bh0, bh1);
                    mma_bf16(acc2[mt][nt], ah[mt][0], ah[mt][1], ah[mt][2], ah[mt][3], bl0, bl1);
                    mma_bf16(acc2[mt][nt], al[mt][0], al[mt][1], al[mt][2], al[mt][3], bh0, bh1);
                }
            }
        }
        __syncthreads();
    }

    #pragma unroll
    for (int mt = 0; mt < 2; mt++) {
        #pragma unroll
        for (int nt = 0; nt < 3; nt++) {
            #pragma unroll
            for (int e = 0; e < 4; e++) {
                int p = row0 + warpM * 32 + mt * 16 + (lane >> 2) + ((e >= 2) ? 8 : 0);
                int o = warpN * 24 + nt * 8 + 2 * (lane & 3) + (e & 1);
                int hw = p & 4095;
                if (o < NCLS)
                    outp[(size_t)bidx * NCLS * HWP + (size_t)o * HWP + hw] =
                        acc2[mt][nt][e] + b_cls[o];
            }
        }
    }
}

// ---------------- kernel 3: smem-tiled depthwise 3x3 + LN(32) + GELU ----------
__global__ void __launch_bounds__(256, 2) k_dw(const float* __restrict__ wdw,
                                               const float* __restrict__ g2,
                                               const float* __restrict__ b2)
{
    extern __shared__ float4 st4[];
    __shared__ float sw[GCC * 9];
    __shared__ float sg[GCC], sb[GCC];

    int bg = blockIdx.x >> 4;
    int h0 = (blockIdx.x & 15) * 4;
    int b = bg >> 1, g = bg & 1;
    int tid = threadIdx.x;

    for (int i = tid; i < GCC * 9; i += 256) sw[i] = wdw[i];
    if (tid < GCC) { sg[tid] = g2[tid]; sb[tid] = b2[tid]; }
    for (int i = tid; i < 3168; i += 256) st4[i] = make_float4(0.f, 0.f, 0.f, 0.f);
    __syncthreads();

    for (int i = tid; i < 3072; i += 256) {
        int c4 = i & 7, col = (i >> 3) & 63, r = i >> 9;
        int gr = h0 - 1 + r;
        if ((unsigned)gr < 64u)
            st4[(c4 * 6 + r) * 66 + col + 1] =
                *(const float4*)(g_qbuf + ((size_t)(b * HWP + gr * 64 + col)) * CRC + g * GCC + c4 * 4);
    }
    __syncthreads();

    int col = tid & 63;
    int row = tid >> 6;
    int h = h0 + row;

    float acc[GCC];
    #pragma unroll
    for (int c = 0; c < GCC; c++) acc[c] = 0.f;

    #pragma unroll
    for (int ky = 0; ky < 3; ky++) {
        #pragma unroll
        for (int kx = 0; kx < 3; kx++) {
            int kidx = ky * 3 + kx;
            #pragma unroll
            for (int c4 = 0; c4 < 8; c4++) {
                float4 v = st4[(c4 * 6 + row + ky) * 66 + col + kx];
                acc[c4 * 4 + 0] += v.x * sw[(c4 * 4 + 0) * 9 + kidx];
                acc[c4 * 4 + 1] += v.y * sw[(c4 * 4 + 1) * 9 + kidx];
                acc[c4 * 4 + 2] += v.z * sw[(c4 * 4 + 2) * 9 + kidx];
                acc[c4 * 4 + 3] += v.w * sw[(c4 * 4 + 3) * 9 + kidx];
            }
        }
    }

    float m = 0.f;
    #pragma unroll
    for (int c = 0; c < GCC; c++) m += acc[c];
    m *= (1.f / GCC);
    float v = 0.f;
    #pragma unroll
    for (int c = 0; c < GCC; c++) { float d = acc[c] - m; v += d * d; }
    float rs = rsqrtf(v * (1.f / GCC) + 1e-5f);

    float* dst = g_tbuf + ((size_t)bg * HWP + h * 64 + col) * GCC;
    #pragma unroll
    for (int c = 0; c < GCC; c++) {
        float t = (acc[c] - m) * rs * sg[c] + sb[c];
        dst[c] = 0.5f * t * (1.f + erff(t * 0.70710678118654752f));
    }
}

// ---------------- kernel 4: smem-tiled 3x3 conv (32->18), 2 rows/block --------
__global__ void __launch_bounds__(256) k_off(const float* __restrict__ woff,
                                             const float* __restrict__ boff,
                                             const float* __restrict__ offset)
{
    extern __shared__ float4 dyn4[];
    float4* st4 = dyn4;
    float*  sw  = (float*)(dyn4 + 2112);
    float4* sw4 = (float4*)sw;

    int bg = blockIdx.x >> 5;
    int h0 = (blockIdx.x & 31) * 2;
    int tid = threadIdx.x;

    for (int i = tid; i < OFFC * GCC * 9; i += 256) {
        int o = i / (GCC * 9); int rem = i - o * (GCC * 9);
        int c = rem / 9; int kidx = rem - c * 9;
        sw[(kidx * OFFC + o) * GCC + c] = woff[i];
    }
    for (int i = tid; i < 2112; i += 256) st4[i] = make_float4(0.f, 0.f, 0.f, 0.f);
    __syncthreads();

    for (int i = tid; i < 2048; i += 256) {
        int c4 = i & 7, col = (i >> 3) & 63, r = i >> 9;
        int gr = h0 - 1 + r;
        if ((unsigned)gr < 64u)
            st4[(c4 * 4 + r) * 66 + col + 1] =
                *(const float4*)(g_tbuf + ((size_t)(bg * HWP + gr * 64 + col)) * GCC + c4 * 4);
    }
    __syncthreads();

    int col = tid & 63;
    int og  = (tid >> 6) & 1;
    int row = tid >> 7;
    int h = h0 + row;
    int b = bg >> 1;

    float acc[9];
    #pragma unroll
    for (int o = 0; o < 9; o++) acc[o] = boff[og * 9 + o];

    #pragma unroll
    for (int c4 = 0; c4 < 8; c4++) {
        #pragma unroll
        for (int ky = 0; ky < 3; ky++) {
            const float4* trow = &st4[(c4 * 4 + row + ky) * 66];
            float4 t[3];
            t[0] = trow[col]; t[1] = trow[col + 1]; t[2] = trow[col + 2];
            #pragma unroll
            for (int kx = 0; kx < 3; kx++) {
                int kidx = ky * 3 + kx;
                #pragma unroll
                for (int o = 0; o < 9; o++) {
                    float4 w = sw4[(kidx * OFFC + og * 9 + o) * 8 + c4];
                    acc[o] += t[kx].x * w.x + t[kx].y * w.y +
                              t[kx].z * w.z + t[kx].w * w.w;
                }
            }
        }
    }

    int hw = h * 64 + col;
    const float* ofs = offset + (size_t)b * OFFC * HWP + hw;
    float* dst = g_offbuf + ((size_t)bg * HWP + hw) * OFFC + og * 9;
    #pragma unroll
    for (int o = 0; o < 9; o++)
        dst[o] = tanhf(acc[o]) * MULF + ofs[(og * 9 + o) * HWP];
}

// ---------------- kernel 5: deformable attention, online softmax ---------------
__device__ __forceinline__ void samp16h(const __half* __restrict__ bufh,
                                        int y, int x, float w, float s[16])
{
    if ((unsigned)x < 64u && (unsigned)y < 64u) {
        const uint4* q = (const uint4*)(bufh + (y * 64 + x) * GCC);
        uint4 u0 = q[0], u1 = q[1];
        const __half2* h0 = (const __half2*)&u0;
        const __half2* h1 = (const __half2*)&u1;
        #pragma unroll
        for (int i = 0; i < 4; i++) {
            float2 f = __half22float2(h0[i]);
            s[2 * i]     += w * f.x;
            s[2 * i + 1] += w * f.y;
        }
        #pragma unroll
        for (int i = 0; i < 4; i++) {
            float2 f = __half22float2(h1[i]);
            s[8 + 2 * i]     += w * f.x;
            s[8 + 2 * i + 1] += w * f.y;
        }
    }
}

__global__ void k_attn(const float* __restrict__ rpb)
{
    int idx = blockIdx.x * blockDim.x + threadIdx.x;
    int nh = idx & 3;
    int p  = idx >> 2;
    int b = p >> 12, hw = p & 4095;
    int g = nh >> 1, hb = (nh & 1) * 16;
    int bg = b * 2 + g;

    float q[16];
    const float* qp = g_qbuf + (size_t)p * CRC + nh * HCC;
    #pragma unroll
    for (int i = 0; i < 16; i++) q[i] = qp[i] * SCALEF;

    const float* off = g_offbuf + (size_t)(bg * HWP + hw) * OFFC;
    const __half* kb = g_kbufh + (size_t)bg * HWP * GCC + hb;
    const __half* vb = g_vbufh + (size_t)bg * HWP * GCC + hb;
    const float* rp = rpb + nh * (N9 * HCC);

    float o16[16];
    #pragma unroll
    for (int i = 0; i < 16; i++) o16[i] = 0.f;
    float m = -3.0e38f, sum = 0.f;

    #pragma unroll
    for (int n = 0; n < N9; n++) {
        float row = off[2 * n], col = off[2 * n + 1];
        float xf = floorf(col), yf = floorf(row);
        int ix = (int)xf, iy = (int)yf;
        float fx = col - xf, fy = row - yf;

        float w00 = (1.f - fx) * (1.f - fy);
        float w10 = fx * (1.f - fy);
        float w01 = (1.f - fx) * fy;
        float w11 = fx * fy;

        // k gather + logit
        float s[16];
        #pragma unroll
        for (int i = 0; i < 16; i++) s[i] = 0.f;
        samp16h(kb, iy,     ix,     w00, s);
        samp16h(kb, iy,     ix + 1, w10, s);
        samp16h(kb, iy + 1, ix,     w01, s);
        samp16h(kb, iy + 1, ix + 1, w11, s);

        float l = 0.f;
        const float* rpn = rp + n * HCC;
        #pragma unroll
        for (int i = 0; i < 16; i++) l += q[i] * (s[i] + rpn[i]);

        // online softmax update
        float mnew = fmaxf(m, l);
        float scale = __expf(m - mnew);
        float e = __expf(l - mnew);
        sum = sum * scale + e;
        m = mnew;

        // v gather into s (reused), weighted by corner weights only
        #pragma unroll
        for (int i = 0; i < 16; i++) s[i] = 0.f;
        samp16h(vb, iy,     ix,     w00, s);
        samp16h(vb, iy,     ix + 1, w10, s);
        samp16h(vb, iy + 1, ix,     w01, s);
        samp16h(vb, iy + 1, ix + 1, w11, s);

        #pragma unroll
        for (int i = 0; i < 16; i++)
            o16[i] = o16[i] * scale + e * s[i];
    }

    float inv = 1.f / sum;
    float* dst = g_attnout + (size_t)p * CRC + nh * HCC;
    #pragma unroll
    for (int i = 0; i < 16; i++) dst[i] = o16[i] * inv;
}

// ---------------- launch ----------------
extern "C" void kernel_launch(void* const* d_in, const int* in_sizes, int n_in,
                              void* d_out, int out_size)
{
    const float* x      = (const float*)d_in[0];
    const float* offset = (const float*)d_in[1];
    const float* ln1_g  = (const float*)d_in[2];
    const float* ln1_b  = (const float*)d_in[3];
    const float* w_qkv  = (const float*)d_in[4];
    const float* w_dw   = (const float*)d_in[5];
    const float* ln2_g  = (const float*)d_in[6];
    const float* ln2_b  = (const float*)d_in[7];
    const float* w_off  = (const float*)d_in[8];
    const float* b_off  = (const float*)d_in[9];
    const float* rpb    = (const float*)d_in[10];
    const float* w_proj = (const float*)d_in[11];
    const float* b_proj = (const float*)d_in[12];
    const float* w_cls  = (const float*)d_in[13];
    const float* b_cls  = (const float*)d_in[14];
    float* out = (float*)d_out;

    const int dwSmem  = 3168 * 16;
    const int offSmem = 2112 * 16 + 5184 * 4;
    const int pcSmem  = 24320 * 4;
    const int lqSmem  = 28032 * 4;
    static int configured = 0;
    if (!configured) {
        cudaFuncSetAttribute(k_dw,  cudaFuncAttributeMaxDynamicSharedMemorySize, dwSmem);
        cudaFuncSetAttribute(k_off, cudaFuncAttributeMaxDynamicSharedMemorySize, offSmem);
        cudaFuncSetAttribute(k_projcls, cudaFuncAttributeMaxDynamicSharedMemorySize, pcSmem);
        cudaFuncSetAttribute(k_lnqkv, cudaFuncAttributeMaxDynamicSharedMemorySize, lqSmem);
        configured = 1;
    }

    k_lnqkv<<<PP / 64, 256, lqSmem>>>(x, ln1_g, ln1_b, w_qkv);
    k_dw<<<16 * 16, 256, dwSmem>>>(w_dw, ln2_g, ln2_b);
    k_off<<<16 * 32, 256, offSmem>>>(w_off, b_off, offset);
    k_attn<<<(PP * 4) / 128, 128>>>(rpb);
    k_projcls<<<PP / 64, 256, pcSmem>>>(w_proj, b_proj, x, w_cls, b_cls, out);
}

// round 17
// speedup vs baseline: 1.2420x; 1.0140x over previous
#include <cuda_runtime.h>
#include <cuda_bf16.h>
#include <cuda_fp16.h>
#include <math.h>

// ---------------- static config ----------------
#define HWP   4096
#define PP    32768
#define DIMC  256
#define CRC   64
#define GCC   32
#define HCC   16
#define N9    9
#define OFFC  18
#define NCLS  80
#define SCALEF 0.25f
#define MULF  5.0f

// ---------------- scratch ----------------
__device__ float  g_qbuf[PP * CRC];
__device__ __half g_kbufh[16 * HWP * GCC];
__device__ __half g_vbufh[16 * HWP * GCC];
__device__ float  g_tbuf[16 * HWP * GCC];
__device__ float  g_offbuf[16 * HWP * OFFC];
__device__ float  g_attnout[PP * CRC];

// ---------------- helpers: bf16 split + mma ----------------
__device__ __forceinline__ void cvt_pair(float x0, float x1,
                                         unsigned& hi, unsigned& lo)
{
    __nv_bfloat16 h0 = __float2bfloat16(x0);
    __nv_bfloat16 h1 = __float2bfloat16(x1);
    float r0 = x0 - __bfloat162float(h0);
    float r1 = x1 - __bfloat162float(h1);
    __nv_bfloat16 l0 = __float2bfloat16(r0);
    __nv_bfloat16 l1 = __float2bfloat16(r1);
    unsigned short u0 = *(unsigned short*)&h0, u1 = *(unsigned short*)&h1;
    unsigned short v0 = *(unsigned short*)&l0, v1 = *(unsigned short*)&l1;
    hi = (unsigned)u0 | ((unsigned)u1 << 16);
    lo = (unsigned)v0 | ((unsigned)v1 << 16);
}

__device__ __forceinline__ void mma_bf16(float* c,
                                         unsigned a0, unsigned a1, unsigned a2, unsigned a3,
                                         unsigned b0, unsigned b1)
{
    asm volatile(
        "mma.sync.aligned.m16n8k16.row.col.f32.bf16.bf16.f32 "
        "{%0,%1,%2,%3}, {%4,%5,%6,%7}, {%8,%9}, {%0,%1,%2,%3};\n"
        : "+f"(c[0]), "+f"(c[1]), "+f"(c[2]), "+f"(c[3])
        : "r"(a0), "r"(a1), "r"(a2), "r"(a3), "r"(b0), "r"(b1));
}

// ---------------- fused LN + qkv GEMM (unchanged) -------------------------
__global__ void __launch_bounds__(256) k_lnqkv(const float* __restrict__ x,
                                               const float* __restrict__ gam,
                                               const float* __restrict__ bet,
                                               const float* __restrict__ Bw)
{
    extern __shared__ unsigned sm[];
    unsigned* Ah = sm;
    unsigned* Al = sm + 10240;
    unsigned* Bh = sm + 20480;
    unsigned* Bl = sm + 23936;
    float* red   = (float*)(sm + 27392);
    float* meanv = red + 512;
    float* rstdv = meanv + 64;

    int tid = threadIdx.x;
    int row0 = blockIdx.x * 64;
    int bidx = row0 >> 12;
    int hw0 = row0 & 4095;
    int col = tid & 63;
    int cg  = tid >> 6;

    const float* xb = x + (size_t)bidx * DIMC * HWP + hw0;

    float sum = 0.f, sq = 0.f;
    #pragma unroll 8
    for (int j = 0; j < 32; j++) {
        int c = (cg + j * 4) * 2;
        float v0 = xb[(size_t)c * HWP + col];
        float v1 = xb[(size_t)(c + 1) * HWP + col];
        sum += v0 + v1;
        sq  += v0 * v0 + v1 * v1;
    }
    red[cg * 64 + col] = sum;
    red[256 + cg * 64 + col] = sq;
    __syncthreads();
    if (tid < 64) {
        float s1 = red[tid] + red[64 + tid] + red[128 + tid] + red[192 + tid];
        float s2 = red[256 + tid] + red[320 + tid] + red[384 + tid] + red[448 + tid];
        float m = s1 * (1.f / 256.f);
        float var = s2 * (1.f / 256.f) - m * m;
        meanv[tid] = m;
        rstdv[tid] = rsqrtf(var + 1e-5f);
    }
    __syncthreads();

    float mm = meanv[col], rs = rstdv[col];
    #pragma unroll 8
    for (int j = 0; j < 32; j++) {
        int pi = cg + j * 4;
        int c = pi * 2;
        float v0 = (xb[(size_t)c * HWP + col] - mm) * rs * __ldg(gam + c) + __ldg(bet + c);
        float v1 = (xb[(size_t)(c + 1) * HWP + col] - mm) * rs * __ldg(gam + c + 1) + __ldg(bet + c + 1);
        unsigned hi, lo;
        cvt_pair(v0, v1, hi, lo);
        int chunk = pi >> 4, slot = pi & 15;
        Ah[chunk * 1280 + col * 20 + slot] = hi;
        Al[chunk * 1280 + col * 20 + slot] = lo;
    }
    __syncthreads();

    int lane = tid & 31;
    int warpId = tid >> 5;
    int warpM = warpId & 1;
    int warpN = warpId >> 1;

    float acc[2][6][4];
    #pragma unroll
    for (int mt = 0; mt < 2; mt++)
        #pragma unroll
        for (int nt = 0; nt < 6; nt++)
            #pragma unroll
            for (int e = 0; e < 4; e++) acc[mt][nt][e] = 0.f;

    for (int ch = 0; ch < 8; ch++) {
        #pragma unroll
        for (int i = 0; i < 6; i++) {
            int u = tid + i * 256;
            int rowb = u >> 3, f = u & 7;
            float4 v = *(const float4*)(Bw + (size_t)rowb * DIMC + ch * 32 + f * 4);
            unsigned h0, l0, h1, l1;
            cvt_pair(v.x, v.y, h0, l0);
            cvt_pair(v.z, v.w, h1, l1);
            Bh[rowb * 18 + f * 2] = h0; Bh[rowb * 18 + f * 2 + 1] = h1;
            Bl[rowb * 18 + f * 2] = l0; Bl[rowb * 18 + f * 2 + 1] = l1;
        }
        __syncthreads();

        const unsigned* Ach = Ah + ch * 1280;
        const unsigned* Acl = Al + ch * 1280;

        #pragma unroll
        for (int kk = 0; kk < 2; kk++) {
            int kb = kk * 8 + (lane & 3);
            unsigned ah[2][4], al[2][4];
            #pragma unroll
            for (int mt = 0; mt < 2; mt++) {
                int ar = warpM * 32 + mt * 16 + (lane >> 2);
                ah[mt][0] = Ach[ar * 20 + kb];       ah[mt][1] = Ach[(ar + 8) * 20 + kb];
                ah[mt][2] = Ach[ar * 20 + kb + 4];   ah[mt][3] = Ach[(ar + 8) * 20 + kb + 4];
                al[mt][0] = Acl[ar * 20 + kb];       al[mt][1] = Acl[(ar + 8) * 20 + kb];
                al[mt][2] = Acl[ar * 20 + kb + 4];   al[mt][3] = Acl[(ar + 8) * 20 + kb + 4];
            }
            #pragma unroll
            for (int nt = 0; nt < 6; nt++) {
                int br = warpN * 48 + nt * 8 + (lane >> 2);
                unsigned bh0 = Bh[br * 18 + kb], bh1 = Bh[br * 18 + kb + 4];
                unsigned bl0 = Bl[br * 18 + kb], bl1 = Bl[br * 18 + kb + 4];
                #pragma unroll
                for (int mt = 0; mt < 2; mt++) {
                    mma_bf16(acc[mt][nt], ah[mt][0], ah[mt][1], ah[mt][2], ah[mt][3], bh0, bh1);
                    mma_bf16(acc[mt][nt], ah[mt][0], ah[mt][1], ah[mt][2], ah[mt][3], bl0, bl1);
                    mma_bf16(acc[mt][nt], al[mt][0], al[mt][1], al[mt][2], al[mt][3], bh0, bh1);
                }
            }
        }
        __syncthreads();
    }

    #pragma unroll
    for (int mt = 0; mt < 2; mt++) {
        #pragma unroll
        for (int nt = 0; nt < 6; nt++) {
            #pragma unroll
            for (int e = 0; e < 4; e++) {
                int p = row0 + warpM * 32 + mt * 16 + (lane >> 2) + ((e >= 2) ? 8 : 0);
                int o = warpN * 48 + nt * 8 + 2 * (lane & 3) + (e & 1);
                float v = acc[mt][nt][e];
                int pb = p >> 12, hw = p & 4095;
                if (o < 64) {
                    g_qbuf[p * 64 + o] = v;
                } else if (o < 128) {
                    int c = o - 64;
                    g_kbufh[((size_t)(pb * 2 + (c >> 5)) * HWP + hw) * GCC + (c & 31)] =
                        __float2half(v);
                } else {
                    int c = o - 128;
                    g_vbufh[((size_t)(pb * 2 + (c >> 5)) * HWP + hw) * GCC + (c & 31)] =
                        __float2half(v);
                }
            }
        }
    }
}

// ---------------- fused proj + residual + cls (unchanged) ----------------
__global__ void __launch_bounds__(256) k_projcls(const float* __restrict__ w_proj,
                                                 const float* __restrict__ b_proj,
                                                 const float* __restrict__ xres,
                                                 const float* __restrict__ w_cls,
                                                 const float* __restrict__ b_cls,
                                                 float* __restrict__ outp)
{
    extern __shared__ unsigned sm[];
    unsigned* yh = sm;
    unsigned* yl = sm + 8320;
    unsigned* Bh = sm + 16640;
    unsigned* Bl = sm + 19200;
    unsigned* Ah = sm + 21760;
    unsigned* Al = sm + 23040;

    int tid = threadIdx.x;
    int lane = tid & 31;
    int warpId = tid >> 5;
    int warpM = warpId & 1;
    int warpN = warpId >> 1;
    int row0 = blockIdx.x * 64;
    int bidx = row0 >> 12;

    for (int nc = 0; nc < 2; nc++) {
        float acc[2][4][4];
        #pragma unroll
        for (int mt = 0; mt < 2; mt++)
            #pragma unroll
            for (int nt = 0; nt < 4; nt++)
                #pragma unroll
                for (int e = 0; e < 4; e++) acc[mt][nt][e] = 0.f;

        for (int k0 = 0; k0 < 64; k0 += 32) {
            #pragma unroll
            for (int i = 0; i < 2; i++) {
                int u = tid + i * 256;
                int row = u >> 3, f = u & 7;
                float4 v = *(const float4*)(g_attnout + (size_t)(row0 + row) * CRC + k0 + f * 4);
                unsigned h0, l0, h1, l1;
                cvt_pair(v.x, v.y, h0, l0);
                cvt_pair(v.z, v.w, h1, l1);
                Ah[row * 20 + f * 2] = h0; Ah[row * 20 + f * 2 + 1] = h1;
                Al[row * 20 + f * 2] = l0; Al[row * 20 + f * 2 + 1] = l1;
            }
            #pragma unroll
            for (int i = 0; i < 4; i++) {
                int u = tid + i * 256;
                int row = u >> 3, f = u & 7;
                float4 v = *(const float4*)(w_proj + (size_t)(nc * 128 + row) * CRC + k0 + f * 4);
                unsigned h0, l0, h1, l1;
                cvt_pair(v.x, v.y, h0, l0);
                cvt_pair(v.z, v.w, h1, l1);
                Bh[row * 20 + f * 2] = h0; Bh[row * 20 + f * 2 + 1] = h1;
                Bl[row * 20 + f * 2] = l0; Bl[row * 20 + f * 2 + 1] = l1;
            }
            __syncthreads();

            #pragma unroll
            for (int kk = 0; kk < 2; kk++) {
                int kb = kk * 8 + (lane & 3);
                unsigned ah[2][4], al[2][4];
                #pragma unroll
                for (int mt = 0; mt < 2; mt++) {
                    int ar = warpM * 32 + mt * 16 + (lane >> 2);
                    ah[mt][0] = Ah[ar * 20 + kb];       ah[mt][1] = Ah[(ar + 8) * 20 + kb];
                    ah[mt][2] = Ah[ar * 20 + kb + 4];   ah[mt][3] = Ah[(ar + 8) * 20 + kb + 4];
                    al[mt][0] = Al[ar * 20 + kb];       al[mt][1] = Al[(ar + 8) * 20 + kb];
                    al[mt][2] = Al[ar * 20 + kb + 4];   al[mt][3] = Al[(ar + 8) * 20 + kb + 4];
                }
                #pragma unroll
                for (int nt = 0; nt < 4; nt++) {
                    int br = warpN * 32 + nt * 8 + (lane >> 2);
                    unsigned bh0 = Bh[br * 20 + kb], bh1 = Bh[br * 20 + kb + 4];
                    unsigned bl0 = Bl[br * 20 + kb], bl1 = Bl[br * 20 + kb + 4];
                    #pragma unroll
                    for (int mt = 0; mt < 2; mt++) {
                        mma_bf16(acc[mt][nt], ah[mt][0], ah[mt][1], ah[mt][2], ah[mt][3], bh0, bh1);
                        mma_bf16(acc[mt][nt], ah[mt][0], ah[mt][1], ah[mt][2], ah[mt][3], bl0, bl1);
                        mma_bf16(acc[mt][nt], al[mt][0], al[mt][1], al[mt][2], al[mt][3], bh0, bh1);
                    }
                }
            }
            __syncthreads();
        }

        #pragma unroll
        for (int mt = 0; mt < 2; mt++) {
            #pragma unroll
            for (int nt = 0; nt < 4; nt++) {
                #pragma unroll
                for (int ep = 0; ep < 2; ep++) {
                    int r = warpM * 32 + mt * 16 + (lane >> 2) + ep * 8;
                    int p = row0 + r;
                    int hw = p & 4095;
                    int o0 = nc * 128 + warpN * 32 + nt * 8 + 2 * (lane & 3);
                    float v0 = acc[mt][nt][ep * 2] + b_proj[o0]
                             + xres[(size_t)bidx * DIMC * HWP + (size_t)o0 * HWP + hw];
                    float v1 = acc[mt][nt][ep * 2 + 1] + b_proj[o0 + 1]
                             + xres[(size_t)bidx * DIMC * HWP + (size_t)(o0 + 1) * HWP + hw];
                    unsigned hi, lo;
                    cvt_pair(v0, v1, hi, lo);
                    yh[r * 130 + (o0 >> 1)] = hi;
                    yl[r * 130 + (o0 >> 1)] = lo;
                }
            }
        }
        __syncthreads();
    }

    float acc2[2][3][4];
    #pragma unroll
    for (int mt = 0; mt < 2; mt++)
        #pragma unroll
        for (int nt = 0; nt < 3; nt++)
            #pragma unroll
            for (int e = 0; e < 4; e++) acc2[mt][nt][e] = 0.f;

    for (int kc = 0; kc < 8; kc++) {
        #pragma unroll
        for (int i = 0; i < 3; i++) {
            int u = tid + i * 256;
            int row = u >> 3, f = u & 7;
            float4 v = make_float4(0.f, 0.f, 0.f, 0.f);
            if (row < NCLS)
                v = *(const float4*)(w_cls + (size_t)row * DIMC + kc * 32 + f * 4);
            unsigned h0, l0, h1, l1;
            cvt_pair(v.x, v.y, h0, l0);
            cvt_pair(v.z, v.w, h1, l1);
            Bh[row * 20 + f * 2] = h0; Bh[row * 20 + f * 2 + 1] = h1;
            Bl[row * 20 + f * 2] = l0; Bl[row * 20 + f * 2 + 1] = l1;
        }
        __syncthreads();

        int kbase = kc * 16;
        #pragma unroll
        for (int kk = 0; kk < 2; kk++) {
            int kb = kk * 8 + (lane & 3);
            unsigned ah[2][4], al[2][4];
            #pragma unroll
            for (int mt = 0; mt < 2; mt++) {
                int ar = warpM * 32 + mt * 16 + (lane >> 2);
                ah[mt][0] = yh[ar * 130 + kbase + kb];
                ah[mt][1] = yh[(ar + 8) * 130 + kbase + kb];
                ah[mt][2] = yh[ar * 130 + kbase + kb + 4];
                ah[mt][3] = yh[(ar + 8) * 130 + kbase + kb + 4];
                al[mt][0] = yl[ar * 130 + kbase + kb];
                al[mt][1] = yl[(ar + 8) * 130 + kbase + kb];
                al[mt][2] = yl[ar * 130 + kbase + kb + 4];
                al[mt][3] = yl[(ar + 8) * 130 + kbase + kb + 4];
            }
            #pragma unroll
            for (int nt = 0; nt < 3; nt++) {
                int br = warpN * 24 + nt * 8 + (lane >> 2);
                unsigned bh0 = Bh[br * 20 + kb], bh1 = Bh[br * 20 + kb + 4];
                unsigned bl0 = Bl[br * 20 + kb], bl1 = Bl[br * 20 + kb + 4];
                #pragma unroll
                for (int mt = 0; mt < 2; mt++) {
                    mma_bf16(acc2[mt][nt], ah[mt][0], ah[mt][1], ah[mt][2], ah[mt][3], bh0, bh1);
                    mma_bf16(acc2[mt][nt], ah[mt][0], ah[mt][1], ah[mt][2], ah[mt][3], bl0, bl1);
                    mma_bf16(acc2[mt][nt], al[mt][0], al[mt][1], al[mt][2], al[mt][3], bh0, bh1);
                }
            }
        }
        __syncthreads();
    }

    #pragma unroll
    for (int mt = 0; mt < 2; mt++) {
        #pragma unroll
        for (int nt = 0; nt < 3; nt++) {
            #pragma unroll
            for (int e = 0; e < 4; e++) {
                int p = row0 + warpM * 32 + mt * 16 + (lane >> 2) + ((e >= 2) ? 8 : 0);
                int o = warpN * 24 + nt * 8 + 2 * (lane & 3) + (e & 1);
                int hw = p & 4095;
                if (o < NCLS)
                    outp[(size_t)bidx * NCLS * HWP + (size_t)o * HWP + hw] =
                        acc2[mt][nt][e] + b_cls[o];
            }
        }
    }
}

// ---------------- kernel 3: smem-tiled depthwise 3x3 + LN(32) + GELU ----------
__global__ void __launch_bounds__(256, 2) k_dw(const float* __restrict__ wdw,
                                               const float* __restrict__ g2,
                                               const float* __restrict__ b2)
{
    extern __shared__ float4 st4[];
    __shared__ float sw[GCC * 9];
    __shared__ float sg[GCC], sb[GCC];

    int bg = blockIdx.x >> 4;
    int h0 = (blockIdx.x & 15) * 4;
    int b = bg >> 1, g = bg & 1;
    int tid = threadIdx.x;

    for (int i = tid; i < GCC * 9; i += 256) sw[i] = wdw[i];
    if (tid < GCC) { sg[tid] = g2[tid]; sb[tid] = b2[tid]; }
    for (int i = tid; i < 3168; i += 256) st4[i] = make_float4(0.f, 0.f, 0.f, 0.f);
    __syncthreads();

    for (int i = tid; i < 3072; i += 256) {
        int c4 = i & 7, col = (i >> 3) & 63, r = i >> 9;
        int gr = h0 - 1 + r;
        if ((unsigned)gr < 64u)
            st4[(c4 * 6 + r) * 66 + col + 1] =
                *(const float4*)(g_qbuf + ((size_t)(b * HWP + gr * 64 + col)) * CRC + g * GCC + c4 * 4);
    }
    __syncthreads();

    int col = tid & 63;
    int row = tid >> 6;
    int h = h0 + row;

    float acc[GCC];
    #pragma unroll
    for (int c = 0; c < GCC; c++) acc[c] = 0.f;

    #pragma unroll
    for (int ky = 0; ky < 3; ky++) {
        #pragma unroll
        for (int kx = 0; kx < 3; kx++) {
            int kidx = ky * 3 + kx;
            #pragma unroll
            for (int c4 = 0; c4 < 8; c4++) {
                float4 v = st4[(c4 * 6 + row + ky) * 66 + col + kx];
                acc[c4 * 4 + 0] += v.x * sw[(c4 * 4 + 0) * 9 + kidx];
                acc[c4 * 4 + 1] += v.y * sw[(c4 * 4 + 1) * 9 + kidx];
                acc[c4 * 4 + 2] += v.z * sw[(c4 * 4 + 2) * 9 + kidx];
                acc[c4 * 4 + 3] += v.w * sw[(c4 * 4 + 3) * 9 + kidx];
            }
        }
    }

    float m = 0.f;
    #pragma unroll
    for (int c = 0; c < GCC; c++) m += acc[c];
    m *= (1.f / GCC);
    float v = 0.f;
    #pragma unroll
    for (int c = 0; c < GCC; c++) { float d = acc[c] - m; v += d * d; }
    float rs = rsqrtf(v * (1.f / GCC) + 1e-5f);

    float* dst = g_tbuf + ((size_t)bg * HWP + h * 64 + col) * GCC;
    #pragma unroll
    for (int c = 0; c < GCC; c++) {
        float t = (acc[c] - m) * rs * sg[c] + sb[c];
        dst[c] = 0.5f * t * (1.f + erff(t * 0.70710678118654752f));
    }
}

// ---------------- kernel 4: smem-tiled 3x3 conv (32->18), 2 rows/block --------
__global__ void __launch_bounds__(256) k_off(const float* __restrict__ woff,
                                             const float* __restrict__ boff,
                                             const float* __restrict__ offset)
{
    extern __shared__ float4 dyn4[];
    float4* st4 = dyn4;
    float*  sw  = (float*)(dyn4 + 2112);
    float4* sw4 = (float4*)sw;

    int bg = blockIdx.x >> 5;
    int h0 = (blockIdx.x & 31) * 2;
    int tid = threadIdx.x;

    for (int i = tid; i < OFFC * GCC * 9; i += 256) {
        int o = i / (GCC * 9); int rem = i - o * (GCC * 9);
        int c = rem / 9; int kidx = rem - c * 9;
        sw[(kidx * OFFC + o) * GCC + c] = woff[i];
    }
    for (int i = tid; i < 2112; i += 256) st4[i] = make_float4(0.f, 0.f, 0.f, 0.f);
    __syncthreads();

    for (int i = tid; i < 2048; i += 256) {
        int c4 = i & 7, col = (i >> 3) & 63, r = i >> 9;
        int gr = h0 - 1 + r;
        if ((unsigned)gr < 64u)
            st4[(c4 * 4 + r) * 66 + col + 1] =
                *(const float4*)(g_tbuf + ((size_t)(bg * HWP + gr * 64 + col)) * GCC + c4 * 4);
    }
    __syncthreads();

    int col = tid & 63;
    int og  = (tid >> 6) & 1;
    int row = tid >> 7;
    int h = h0 + row;
    int b = bg >> 1;

    float acc[9];
    #pragma unroll
    for (int o = 0; o < 9; o++) acc[o] = boff[og * 9 + o];

    #pragma unroll
    for (int c4 = 0; c4 < 8; c4++) {
        #pragma unroll
        for (int ky = 0; ky < 3; ky++) {
            const float4* trow = &st4[(c4 * 4 + row + ky) * 66];
            float4 t[3];
            t[0] = trow[col]; t[1] = trow[col + 1]; t[2] = trow[col + 2];
            #pragma unroll
            for (int kx = 0; kx < 3; kx++) {
                int kidx = ky * 3 + kx;
                #pragma unroll
                for (int o = 0; o < 9; o++) {
                    float4 w = sw4[(kidx * OFFC + og * 9 + o) * 8 + c4];
                    acc[o] += t[kx].x * w.x + t[kx].y * w.y +
                              t[kx].z * w.z + t[kx].w * w.w;
                }
            }
        }
    }

    int hw = h * 64 + col;
    const float* ofs = offset + (size_t)b * OFFC * HWP + hw;
    float* dst = g_offbuf + ((size_t)bg * HWP + hw) * OFFC + og * 9;
    #pragma unroll
    for (int o = 0; o < 9; o++)
        dst[o] = tanhf(acc[o]) * MULF + ofs[(og * 9 + o) * HWP];
}

// ---------------- kernel 5: deformable attention, online softmax, vec loads ----
__device__ __forceinline__ void samp16h(const __half* __restrict__ bufh,
                                        int y, int x, float w, float s[16])
{
    if ((unsigned)x < 64u && (unsigned)y < 64u) {
        const uint4* q = (const uint4*)(bufh + (y * 64 + x) * GCC);
        uint4 u0 = q[0], u1 = q[1];
        const __half2* h0 = (const __half2*)&u0;
        const __half2* h1 = (const __half2*)&u1;
        #pragma unroll
        for (int i = 0; i < 4; i++) {
            float2 f = __half22float2(h0[i]);
            s[2 * i]     += w * f.x;
            s[2 * i + 1] += w * f.y;
        }
        #pragma unroll
        for (int i = 0; i < 4; i++) {
            float2 f = __half22float2(h1[i]);
            s[8 + 2 * i]     += w * f.x;
            s[8 + 2 * i + 1] += w * f.y;
        }
    }
}

__global__ void k_attn(const float* __restrict__ rpb)
{
    int idx = blockIdx.x * blockDim.x + threadIdx.x;
    int nh = idx & 3;
    int p  = idx >> 2;
    int b = p >> 12, hw = p & 4095;
    int g = nh >> 1, hb = (nh & 1) * 16;
    int bg = b * 2 + g;

    float q[16];
    {
        const float4* qp = (const float4*)(g_qbuf + (size_t)p * CRC + nh * HCC);
        #pragma unroll
        for (int j = 0; j < 4; j++) {
            float4 t = qp[j];
            q[4 * j]     = t.x * SCALEF;
            q[4 * j + 1] = t.y * SCALEF;
            q[4 * j + 2] = t.z * SCALEF;
            q[4 * j + 3] = t.w * SCALEF;
        }
    }

    const float* off = g_offbuf + (size_t)(bg * HWP + hw) * OFFC;
    const __half* kb = g_kbufh + (size_t)bg * HWP * GCC + hb;
    const __half* vb = g_vbufh + (size_t)bg * HWP * GCC + hb;
    const float4* rp4 = (const float4*)(rpb + nh * (N9 * HCC));

    float o16[16];
    #pragma unroll
    for (int i = 0; i < 16; i++) o16[i] = 0.f;
    float m = -3.0e38f, sum = 0.f;

    #pragma unroll
    for (int n = 0; n < N9; n++) {
        float row = off[2 * n], col = off[2 * n + 1];
        float xf = floorf(col), yf = floorf(row);
        int ix = (int)xf, iy = (int)yf;
        float fx = col - xf, fy = row - yf;

        float w00 = (1.f - fx) * (1.f - fy);
        float w10 = fx * (1.f - fy);
        float w01 = (1.f - fx) * fy;
        float w11 = fx * fy;

        // k gather + logit
        float s[16];
        #pragma unroll
        for (int i = 0; i < 16; i++) s[i] = 0.f;
        samp16h(kb, iy,     ix,     w00, s);
        samp16h(kb, iy,     ix + 1, w10, s);
        samp16h(kb, iy + 1, ix,     w01, s);
        samp16h(kb, iy + 1, ix + 1, w11, s);

        float l = 0.f;
        #pragma unroll
        for (int j = 0; j < 4; j++) {
            float4 r4 = rp4[n * 4 + j];
            l += q[4 * j]     * (s[4 * j]     + r4.x);
            l += q[4 * j + 1] * (s[4 * j + 1] + r4.y);
            l += q[4 * j + 2] * (s[4 * j + 2] + r4.z);
            l += q[4 * j + 3] * (s[4 * j + 3] + r4.w);
        }

        // online softmax update
        float mnew = fmaxf(m, l);
        float scale = __expf(m - mnew);
        float e = __expf(l - mnew);
        sum = sum * scale + e;
        m = mnew;

        // v gather into s (reused)
        #pragma unroll
        for (int i = 0; i < 16; i++) s[i] = 0.f;
        samp16h(vb, iy,     ix,     w00, s);
        samp16h(vb, iy,     ix + 1, w10, s);
        samp16h(vb, iy + 1, ix,     w01, s);
        samp16h(vb, iy + 1, ix + 1, w11, s);

        #pragma unroll
        for (int i = 0; i < 16; i++)
            o16[i] = o16[i] * scale + e * s[i];
    }

    float inv = 1.f / sum;
    float4* dst = (float4*)(g_attnout + (size_t)p * CRC + nh * HCC);
    #pragma unroll
    for (int j = 0; j < 4; j++)
        dst[j] = make_float4(o16[4 * j] * inv, o16[4 * j + 1] * inv,
                             o16[4 * j + 2] * inv, o16[4 * j + 3] * inv);
}

// ---------------- launch ----------------
extern "C" void kernel_launch(void* const* d_in, const int* in_sizes, int n_in,
                              void* d_out, int out_size)
{
    const float* x      = (const float*)d_in[0];
    const float* offset = (const float*)d_in[1];
    const float* ln1_g  = (const float*)d_in[2];
    const float* ln1_b  = (const float*)d_in[3];
    const float* w_qkv  = (const float*)d_in[4];
    const float* w_dw   = (const float*)d_in[5];
    const float* ln2_g  = (const float*)d_in[6];
    const float* ln2_b  = (const float*)d_in[7];
    const float* w_off  = (const float*)d_in[8];
    const float* b_off  = (const float*)d_in[9];
    const float* rpb    = (const float*)d_in[10];
    const float* w_proj = (const float*)d_in[11];
    const float* b_proj = (const float*)d_in[12];
    const float* w_cls  = (const float*)d_in[13];
    const float* b_cls  = (const float*)d_in[14];
    float* out = (float*)d_out;

    const int dwSmem  = 3168 * 16;
    const int offSmem = 2112 * 16 + 5184 * 4;
    const int pcSmem  = 24320 * 4;
    const int lqSmem  = 28032 * 4;
    static int configured = 0;
    if (!configured) {
        cudaFuncSetAttribute(k_dw,  cudaFuncAttributeMaxDynamicSharedMemorySize, dwSmem);
        cudaFuncSetAttribute(k_off, cudaFuncAttributeMaxDynamicSharedMemorySize, offSmem);
        cudaFuncSetAttribute(k_projcls, cudaFuncAttributeMaxDynamicSharedMemorySize, pcSmem);
        cudaFuncSetAttribute(k_lnqkv, cudaFuncAttributeMaxDynamicSharedMemorySize, lqSmem);
        configured = 1;
    }

    k_lnqkv<<<PP / 64, 256, lqSmem>>>(x, ln1_g, ln1_b, w_qkv);
    k_dw<<<16 * 16, 256, dwSmem>>>(w_dw, ln2_g, ln2_b);
    k_off<<<16 * 32, 256, offSmem>>>(w_off, b_off, offset);
    k_attn<<<(PP * 4) / 128, 128>>>(rpb);
    k_projcls<<<PP / 64, 256, pcSmem>>>(w_proj, b_proj, x, w_cls, b_cls, out);
}